// round 1
// baseline (speedup 1.0000x reference)
#include <cuda_runtime.h>
#include <math.h>

// Problem constants
#define NB  2
#define NS  2048
#define ND  1024
#define NH  16
#define NHD 64
#define SCALE 0.125f   // 1/sqrt(64)

// Scratch (allocation-free contract: __device__ globals)
__device__ float g_q[NB * NH * NS * NHD];      // [b,h,s,hd]
__device__ float g_k[NB * NH * NS * NHD];
__device__ float g_v[NB * NH * NS * NHD];
__device__ float g_attn[NB * NS * ND];         // [b,s,d]

// ---------------------------------------------------------------------------
// Classic 128x128x8 SGEMM, 256 threads, 8x8 per-thread register tile.
// MODE 0: epilogue scatters QKV into g_q/g_k/g_v ([b,h,s,hd] layout), +bias
// MODE 1: epilogue writes C[m*N+n] = acc + bias[n]
// M,N,K must be multiples of 128/128/8 (they are: 4096 x {3072,1024} x 1024).
// ---------------------------------------------------------------------------
template <int MODE>
__global__ __launch_bounds__(256) void sgemm128(
    const float* __restrict__ A, const float* __restrict__ Bm,
    const float* __restrict__ bias, float* __restrict__ C,
    int M, int N, int K)
{
    __shared__ float As[8][128];
    __shared__ float Bs[8][128];

    const int t  = threadIdx.x;
    const int tx = t & 15;       // 0..15 -> 8 output cols each
    const int ty = t >> 4;       // 0..15 -> 8 output rows each
    const int bm = blockIdx.y * 128;
    const int bn = blockIdx.x * 128;

    const int arow = t >> 1;           // 0..127
    const int acol = (t & 1) * 4;      // 0 or 4
    const int brow = t >> 5;           // 0..7
    const int bcol = (t & 31) * 4;     // 0..124

    const float* Aptr = A + (size_t)(bm + arow) * K + acol;
    const float* Bptr = Bm + (size_t)brow * N + bn + bcol;

    float acc[8][8];
#pragma unroll
    for (int i = 0; i < 8; i++)
#pragma unroll
        for (int j = 0; j < 8; j++) acc[i][j] = 0.f;

    for (int k0 = 0; k0 < K; k0 += 8) {
        float4 a4 = *(const float4*)(Aptr + k0);
        float4 b4 = *(const float4*)(Bptr + (size_t)k0 * N);
        As[acol + 0][arow] = a4.x;
        As[acol + 1][arow] = a4.y;
        As[acol + 2][arow] = a4.z;
        As[acol + 3][arow] = a4.w;
        *(float4*)&Bs[brow][bcol] = b4;
        __syncthreads();

#pragma unroll
        for (int kk = 0; kk < 8; kk++) {
            float ar[8], br[8];
            *(float4*)&ar[0] = *(const float4*)&As[kk][ty * 8];
            *(float4*)&ar[4] = *(const float4*)&As[kk][ty * 8 + 4];
            *(float4*)&br[0] = *(const float4*)&Bs[kk][tx * 8];
            *(float4*)&br[4] = *(const float4*)&Bs[kk][tx * 8 + 4];
#pragma unroll
            for (int i = 0; i < 8; i++)
#pragma unroll
                for (int j = 0; j < 8; j++)
                    acc[i][j] = fmaf(ar[i], br[j], acc[i][j]);
        }
        __syncthreads();
    }

#pragma unroll
    for (int i = 0; i < 8; i++) {
        const int m = bm + ty * 8 + i;
#pragma unroll
        for (int j = 0; j < 8; j++) {
            const int n = bn + tx * 8 + j;
            const float v = acc[i][j] + bias[n];
            if (MODE == 0) {
                // m = b*NS + s ; n = which*ND + h*NHD + hd
                const int b = m >> 11;            // NS = 2048
                const int s = m & (NS - 1);
                const int which = n >> 10;        // ND = 1024
                const int dcol  = n & (ND - 1);
                const int h  = dcol >> 6;         // NHD = 64
                const int hd = dcol & 63;
                float* dst = (which == 0) ? g_q : (which == 1) ? g_k : g_v;
                dst[((size_t)((b * NH + h) * NS + s)) * NHD + hd] = v;
            } else {
                C[(size_t)m * N + n] = v;
            }
        }
    }
}

// ---------------------------------------------------------------------------
// Flash attention, fp32. Block = 128 threads, tile 64 q-rows x 64 k-cols.
// Thread (rg = t>>3, cg = t&7) owns rows rg*4+{0..3}, cols cg+8*{0..7}.
// Strided column ownership -> conflict-free LDS patterns on Ks/Vs,
// 8-lane shfl_xor(1,2,4) reductions over column groups for softmax.
// Dynamic smem: Qs,Ks,Vs,Ps each [64][65] floats = 66560 bytes.
// ---------------------------------------------------------------------------
#define ATTN_SMEM (4 * 64 * 65 * 4)

__global__ __launch_bounds__(128) void attn64()
{
    extern __shared__ float sm[];
    float (*Qs)[65] = (float(*)[65])(sm);
    float (*Ks)[65] = (float(*)[65])(sm + 64 * 65);
    float (*Vs)[65] = (float(*)[65])(sm + 2 * 64 * 65);
    float (*Ps)[65] = (float(*)[65])(sm + 3 * 64 * 65);

    const int t  = threadIdx.x;
    const int cg = t & 7;
    const int rg = t >> 3;
    const int qt = blockIdx.x;       // 0..31
    const int bh = blockIdx.y;       // 0..31  (b*NH + h)

    const size_t base = (size_t)bh * NS * NHD;
    const float* Qg = g_q + base + (size_t)qt * 64 * NHD;

    // Load Q tile (pre-scaled)
#pragma unroll
    for (int it = 0; it < 8; it++) {
        const int f4  = t + it * 128;        // 0..1023 float4s
        const int row = f4 >> 4;
        const int c4  = (f4 & 15) << 2;
        float4 v = *(const float4*)(Qg + row * NHD + c4);
        Qs[row][c4 + 0] = v.x * SCALE;
        Qs[row][c4 + 1] = v.y * SCALE;
        Qs[row][c4 + 2] = v.z * SCALE;
        Qs[row][c4 + 3] = v.w * SCALE;
    }

    float o[4][8];
#pragma unroll
    for (int i = 0; i < 4; i++)
#pragma unroll
        for (int j = 0; j < 8; j++) o[i][j] = 0.f;
    float mr[4] = {-INFINITY, -INFINITY, -INFINITY, -INFINITY};
    float lr[4] = {0.f, 0.f, 0.f, 0.f};

    for (int kt = 0; kt <= qt; kt++) {
        __syncthreads();   // prior iteration's reads of Ks/Vs/Ps complete
        const float* Kg = g_k + base + (size_t)kt * 64 * NHD;
        const float* Vg = g_v + base + (size_t)kt * 64 * NHD;
#pragma unroll
        for (int it = 0; it < 8; it++) {
            const int f4  = t + it * 128;
            const int row = f4 >> 4;
            const int c4  = (f4 & 15) << 2;
            float4 kv4 = *(const float4*)(Kg + row * NHD + c4);
            float4 vv4 = *(const float4*)(Vg + row * NHD + c4);
            Ks[row][c4 + 0] = kv4.x; Ks[row][c4 + 1] = kv4.y;
            Ks[row][c4 + 2] = kv4.z; Ks[row][c4 + 3] = kv4.w;
            Vs[row][c4 + 0] = vv4.x; Vs[row][c4 + 1] = vv4.y;
            Vs[row][c4 + 2] = vv4.z; Vs[row][c4 + 3] = vv4.w;
        }
        __syncthreads();

        // ---- scores S = Q * K^T (tile) ----
        float s[4][8];
#pragma unroll
        for (int i = 0; i < 4; i++)
#pragma unroll
            for (int j = 0; j < 8; j++) s[i][j] = 0.f;

#pragma unroll 8
        for (int d = 0; d < 64; d++) {
            float kv[8];
#pragma unroll
            for (int j = 0; j < 8; j++) kv[j] = Ks[cg + (j << 3)][d];
#pragma unroll
            for (int i = 0; i < 4; i++) {
                const float qv = Qs[(rg << 2) + i][d];
#pragma unroll
                for (int j = 0; j < 8; j++)
                    s[i][j] = fmaf(qv, kv[j], s[i][j]);
            }
        }

        // ---- causal mask on diagonal tile ----
        if (kt == qt) {
#pragma unroll
            for (int i = 0; i < 4; i++)
#pragma unroll
                for (int j = 0; j < 8; j++)
                    if (cg + (j << 3) > (rg << 2) + i) s[i][j] = -INFINITY;
        }

        // ---- online softmax update ----
#pragma unroll
        for (int i = 0; i < 4; i++) {
            float tm = s[i][0];
#pragma unroll
            for (int j = 1; j < 8; j++) tm = fmaxf(tm, s[i][j]);
            tm = fmaxf(tm, __shfl_xor_sync(0xffffffffu, tm, 1));
            tm = fmaxf(tm, __shfl_xor_sync(0xffffffffu, tm, 2));
            tm = fmaxf(tm, __shfl_xor_sync(0xffffffffu, tm, 4));
            const float nm   = fmaxf(mr[i], tm);
            const float corr = __expf(mr[i] - nm);
            mr[i] = nm;
            float ls = 0.f;
#pragma unroll
            for (int j = 0; j < 8; j++) {
                const float p = __expf(s[i][j] - nm);
                s[i][j] = p;
                ls += p;
            }
            ls += __shfl_xor_sync(0xffffffffu, ls, 1);
            ls += __shfl_xor_sync(0xffffffffu, ls, 2);
            ls += __shfl_xor_sync(0xffffffffu, ls, 4);
            lr[i] = lr[i] * corr + ls;
#pragma unroll
            for (int j = 0; j < 8; j++) o[i][j] *= corr;
        }

        // ---- stage P tile, then O += P * V ----
#pragma unroll
        for (int i = 0; i < 4; i++)
#pragma unroll
            for (int j = 0; j < 8; j++)
                Ps[(rg << 2) + i][cg + (j << 3)] = s[i][j];
        __syncthreads();

#pragma unroll 8
        for (int c = 0; c < 64; c++) {
            float vv[8];
#pragma unroll
            for (int j = 0; j < 8; j++) vv[j] = Vs[c][cg + (j << 3)];
#pragma unroll
            for (int i = 0; i < 4; i++) {
                const float p = Ps[(rg << 2) + i][c];
#pragma unroll
                for (int j = 0; j < 8; j++)
                    o[i][j] = fmaf(p, vv[j], o[i][j]);
            }
        }
    }

    // ---- normalize + write attention output in [b,s,d] layout ----
    const int b = bh >> 4;          // NH = 16
    const int h = bh & (NH - 1);
#pragma unroll
    for (int i = 0; i < 4; i++) {
        const float inv  = 1.0f / lr[i];
        const int   srow = qt * 64 + (rg << 2) + i;
        float* dst = g_attn + ((size_t)(b * NS + srow)) * ND + h * NHD;
#pragma unroll
        for (int j = 0; j < 8; j++)
            dst[cg + (j << 3)] = o[i][j] * inv;
    }
}

// ---------------------------------------------------------------------------
// kernel_launch: QKV GEMM -> flash attention -> proj GEMM
// Inputs: x, W_qkv, b_qkv, W_proj, b_proj (all fp32). Output fp32 [B,S,D].
// ---------------------------------------------------------------------------
extern "C" void kernel_launch(void* const* d_in, const int* in_sizes, int n_in,
                              void* d_out, int out_size)
{
    (void)in_sizes; (void)n_in; (void)out_size;
    const float* x     = (const float*)d_in[0];
    const float* Wqkv  = (const float*)d_in[1];
    const float* bqkv  = (const float*)d_in[2];
    const float* Wproj = (const float*)d_in[3];
    const float* bproj = (const float*)d_in[4];
    float* out = (float*)d_out;

    void* p = nullptr;
    cudaGetSymbolAddress(&p, g_attn);
    float* attnp = (float*)p;

    // 1) QKV projection: [4096,1024] x [1024,3072] -> scatter q/k/v
    {
        dim3 grid(3 * ND / 128, (NB * NS) / 128);   // 24 x 32
        sgemm128<0><<<grid, 256>>>(x, Wqkv, bqkv, nullptr, NB * NS, 3 * ND, ND);
    }

    // 2) causal flash attention -> g_attn [b,s,d]
    {
        cudaFuncSetAttribute((const void*)attn64,
                             cudaFuncAttributeMaxDynamicSharedMemorySize,
                             ATTN_SMEM);
        dim3 grid(NS / 64, NB * NH);                // 32 x 32
        attn64<<<grid, 128, ATTN_SMEM>>>();
    }

    // 3) output projection: [4096,1024] x [1024,1024] -> d_out
    {
        dim3 grid(ND / 128, (NB * NS) / 128);       // 8 x 32
        sgemm128<1><<<grid, 256>>>(attnp, Wproj, bproj, out, NB * NS, ND, ND);
    }
}

// round 3
// speedup vs baseline: 1.3137x; 1.3137x over previous
#include <cuda_runtime.h>
#include <math.h>
#include <stdint.h>

// Problem constants
#define NB  2
#define NS  2048
#define ND  1024
#define NH  16
#define NHD 64
#define SCALE 0.125f   // 1/sqrt(64)

// ---------------------------------------------------------------------------
// Scratch (allocation-free contract: __device__ globals)
// ---------------------------------------------------------------------------
__device__ float g_q[NB * NH * NS * NHD];      // [b,h,s,hd]
__device__ float g_k[NB * NH * NS * NHD];
__device__ float g_v[NB * NH * NS * NHD];
__device__ float g_attn[NB * NS * ND];         // [b,s,d]
__device__ float g_ahi[NB * NS * ND];          // hi/lo split of activations
__device__ float g_alo[NB * NS * ND];
__device__ float g_wqh[3 * ND * ND];           // W_qkv^T hi  [3072 x 1024]
__device__ float g_wql[3 * ND * ND];           // W_qkv^T lo
__device__ float g_wph[ND * ND];               // W_proj^T hi [1024 x 1024]
__device__ float g_wpl[ND * ND];               // W_proj^T lo

// ---------------------------------------------------------------------------
// Helpers
// ---------------------------------------------------------------------------
__device__ __forceinline__ uint32_t smem_u32(const void* p) {
    uint32_t a;
    asm("{ .reg .u64 t; cvta.to.shared.u64 t, %1; cvt.u32.u64 %0, t; }"
        : "=r"(a) : "l"(p));
    return a;
}

__device__ __forceinline__ void cp_async16(uint32_t saddr, const void* gptr) {
    asm volatile("cp.async.cg.shared.global [%0], [%1], 16;" :: "r"(saddr), "l"(gptr));
}
#define CP_COMMIT() asm volatile("cp.async.commit_group;" ::: "memory")

__device__ __forceinline__ void split_tf32(float v, float& hi, float& lo) {
    uint32_t u;
    asm("cvt.rna.tf32.f32 %0, %1;" : "=r"(u) : "f"(v));
    hi = __uint_as_float(u);
    float r = v - hi;
    uint32_t u2;
    asm("cvt.rna.tf32.f32 %0, %1;" : "=r"(u2) : "f"(r));
    lo = __uint_as_float(u2);
}

// m16n8k8 tf32 MMA, fp32 accumulate in-place
__device__ __forceinline__ void mma_tf32(float* d, const uint32_t* a, const uint32_t* b) {
    asm volatile(
        "mma.sync.aligned.m16n8k8.row.col.f32.tf32.tf32.f32 "
        "{%0,%1,%2,%3}, {%4,%5,%6,%7}, {%8,%9}, {%0,%1,%2,%3};"
        : "+f"(d[0]), "+f"(d[1]), "+f"(d[2]), "+f"(d[3])
        : "r"(a[0]), "r"(a[1]), "r"(a[2]), "r"(a[3]), "r"(b[0]), "r"(b[1]));
}

// ---------------------------------------------------------------------------
// Prep kernels: tf32 hi/lo split, and transpose+split for weights
// ---------------------------------------------------------------------------
__global__ void split_kernel(const float* __restrict__ in,
                             float* __restrict__ hi, float* __restrict__ lo, int n) {
    for (int i = blockIdx.x * blockDim.x + threadIdx.x; i < n; i += gridDim.x * blockDim.x) {
        float h, l;
        split_tf32(in[i], h, l);
        hi[i] = h;
        lo[i] = l;
    }
}

// W [K,N] row-major  ->  T [N,K] row-major (hi/lo split)
__global__ __launch_bounds__(256) void tsplit_kernel(
    const float* __restrict__ W, float* __restrict__ Thi, float* __restrict__ Tlo,
    int K, int N) {
    __shared__ float tile[32][33];
    const int tx = threadIdx.x;         // 0..31
    const int ty = threadIdx.y;         // 0..7
    const int n0 = blockIdx.x * 32;
    const int k0 = blockIdx.y * 32;
#pragma unroll
    for (int i = 0; i < 32; i += 8)
        tile[ty + i][tx] = W[(size_t)(k0 + ty + i) * N + n0 + tx];
    __syncthreads();
#pragma unroll
    for (int i = 0; i < 32; i += 8) {
        float v = tile[tx][ty + i];
        float h, l;
        split_tf32(v, h, l);
        Thi[(size_t)(n0 + ty + i) * K + k0 + tx] = h;
        Tlo[(size_t)(n0 + ty + i) * K + k0 + tx] = l;
    }
}

// ---------------------------------------------------------------------------
// 3xTF32 mma.sync GEMM: C[M,N] = A[M,K] * B[N,K]^T  (B stored [N,K])
// 128x128 tile/CTA, 256 threads, warps 2(m) x 4(n), warp tile 64x32.
// K-chunk 32, double-buffered cp.async. fp32 accum in registers.
// MODE 0: scatter QKV into g_q/g_k/g_v with bias;  MODE 1: C = acc + bias.
// ---------------------------------------------------------------------------
#define KC     32
#define APAD   4
#define ROWF   (KC + APAD)            // 36 floats per smem row
#define TILEF  (128 * ROWF)           // 4608 floats per tile
#define STAGEF (4 * TILEF)            // Ahi, Alo, Bhi, Blo
#define GEMM_SMEM (2 * STAGEF * 4)    // 147456 bytes

template <int MODE>
__global__ __launch_bounds__(256, 1) void gemm_mma(
    const float* __restrict__ Ahi, const float* __restrict__ Alo,
    const float* __restrict__ Bhi, const float* __restrict__ Blo,
    const float* __restrict__ bias, float* __restrict__ C,
    int M, int N, int K)
{
    extern __shared__ float smf[];
    const int tid  = threadIdx.x;
    const int lane = tid & 31;
    const int wid  = tid >> 5;
    const int wm   = wid >> 2;        // 0..1
    const int wn   = wid & 3;         // 0..3
    const int g    = lane >> 2;       // 0..7
    const int tg   = lane & 3;        // 0..3
    const int bm = blockIdx.y * 128;
    const int bn = blockIdx.x * 128;

    const float* srcT[4] = {Ahi, Alo, Bhi, Blo};

    // stage loader: 4 tiles of 128 rows x 32 floats each
    auto load_stage = [&](int c, int s) {
        const int k0 = c * KC;
        float* stage = smf + s * STAGEF;
#pragma unroll
        for (int t = 0; t < 4; t++) {
            const float* src = srcT[t];
            const int rbase = (t < 2) ? bm : bn;
            float* dst = stage + t * TILEF;
#pragma unroll
            for (int i = 0; i < 4; i++) {
                const int idx = tid + i * 256;     // 0..1023
                const int r = idx >> 3;
                const int q = idx & 7;
                const float* gp = src + (size_t)(rbase + r) * K + k0 + q * 4;
                cp_async16(smem_u32(dst + r * ROWF + q * 4), gp);
            }
        }
        CP_COMMIT();
    };

    float acc[4][4][4];
#pragma unroll
    for (int i = 0; i < 4; i++)
#pragma unroll
        for (int j = 0; j < 4; j++)
#pragma unroll
            for (int kq = 0; kq < 4; kq++) acc[i][j][kq] = 0.f;

    const int NCH = K / KC;
    load_stage(0, 0);

    for (int c = 0; c < NCH; c++) {
        const int s = c & 1;
        if (c + 1 < NCH) {
            load_stage(c + 1, (c + 1) & 1);
            asm volatile("cp.async.wait_group 1;" ::: "memory");
        } else {
            asm volatile("cp.async.wait_group 0;" ::: "memory");
        }
        __syncthreads();

        const float* Ah = smf + s * STAGEF;
        const float* Al = Ah + TILEF;
        const float* Bh = Ah + 2 * TILEF;
        const float* Bl = Ah + 3 * TILEF;

#pragma unroll
        for (int ks = 0; ks < 4; ks++) {
            const int kb = ks * 8;
            uint32_t ah[4][4], al[4][4], bh[4][2], bl[4][2];
#pragma unroll
            for (int am = 0; am < 4; am++) {
                const int r0 = wm * 64 + am * 16 + g;
                ah[am][0] = __float_as_uint(Ah[(r0    ) * ROWF + kb + tg    ]);
                ah[am][1] = __float_as_uint(Ah[(r0 + 8) * ROWF + kb + tg    ]);
                ah[am][2] = __float_as_uint(Ah[(r0    ) * ROWF + kb + tg + 4]);
                ah[am][3] = __float_as_uint(Ah[(r0 + 8) * ROWF + kb + tg + 4]);
                al[am][0] = __float_as_uint(Al[(r0    ) * ROWF + kb + tg    ]);
                al[am][1] = __float_as_uint(Al[(r0 + 8) * ROWF + kb + tg    ]);
                al[am][2] = __float_as_uint(Al[(r0    ) * ROWF + kb + tg + 4]);
                al[am][3] = __float_as_uint(Al[(r0 + 8) * ROWF + kb + tg + 4]);
            }
#pragma unroll
            for (int an = 0; an < 4; an++) {
                const int n0 = wn * 32 + an * 8 + g;
                bh[an][0] = __float_as_uint(Bh[n0 * ROWF + kb + tg    ]);
                bh[an][1] = __float_as_uint(Bh[n0 * ROWF + kb + tg + 4]);
                bl[an][0] = __float_as_uint(Bl[n0 * ROWF + kb + tg    ]);
                bl[an][1] = __float_as_uint(Bl[n0 * ROWF + kb + tg + 4]);
            }
#pragma unroll
            for (int am = 0; am < 4; am++)
#pragma unroll
                for (int an = 0; an < 4; an++) {
                    mma_tf32(acc[am][an], ah[am], bh[an]);   // hi*hi
                    mma_tf32(acc[am][an], ah[am], bl[an]);   // hi*lo
                    mma_tf32(acc[am][an], al[am], bh[an]);   // lo*hi
                }
        }
        __syncthreads();
    }

    // ---- epilogue ----
#pragma unroll
    for (int am = 0; am < 4; am++) {
        const int row0 = bm + wm * 64 + am * 16 + g;
#pragma unroll
        for (int an = 0; an < 4; an++) {
            const int col = bn + wn * 32 + an * 8 + 2 * tg;
            const float v00 = acc[am][an][0] + bias[col];
            const float v01 = acc[am][an][1] + bias[col + 1];
            const float v10 = acc[am][an][2] + bias[col];
            const float v11 = acc[am][an][3] + bias[col + 1];
            if (MODE == 0) {
#pragma unroll
                for (int e = 0; e < 4; e++) {
                    const int m = (e < 2) ? row0 : row0 + 8;
                    const int n = col + (e & 1);
                    const float v = (e == 0) ? v00 : (e == 1) ? v01 : (e == 2) ? v10 : v11;
                    const int b = m >> 11;            // NS = 2048
                    const int srow = m & (NS - 1);
                    const int which = n >> 10;        // ND = 1024
                    const int dcol  = n & (ND - 1);
                    const int h  = dcol >> 6;         // NHD = 64
                    const int hd = dcol & 63;
                    float* dst = (which == 0) ? g_q : (which == 1) ? g_k : g_v;
                    dst[((size_t)((b * NH + h) * NS + srow)) * NHD + hd] = v;
                }
            } else {
                *(float2*)(C + (size_t)row0 * N + col)       = make_float2(v00, v01);
                *(float2*)(C + (size_t)(row0 + 8) * N + col) = make_float2(v10, v11);
            }
        }
    }
}

// ---------------------------------------------------------------------------
// Flash attention, fp32 (unchanged). 64x64 tiles, 128 threads.
// ---------------------------------------------------------------------------
#define ATTN_SMEM (4 * 64 * 65 * 4)

__global__ __launch_bounds__(128) void attn64()
{
    extern __shared__ float sm[];
    float (*Qs)[65] = (float(*)[65])(sm);
    float (*Ks)[65] = (float(*)[65])(sm + 64 * 65);
    float (*Vs)[65] = (float(*)[65])(sm + 2 * 64 * 65);
    float (*Ps)[65] = (float(*)[65])(sm + 3 * 64 * 65);

    const int t  = threadIdx.x;
    const int cg = t & 7;
    const int rg = t >> 3;
    const int qt = blockIdx.x;
    const int bh = blockIdx.y;

    const size_t base = (size_t)bh * NS * NHD;
    const float* Qg = g_q + base + (size_t)qt * 64 * NHD;

#pragma unroll
    for (int it = 0; it < 8; it++) {
        const int f4  = t + it * 128;
        const int row = f4 >> 4;
        const int c4  = (f4 & 15) << 2;
        float4 v = *(const float4*)(Qg + row * NHD + c4);
        Qs[row][c4 + 0] = v.x * SCALE;
        Qs[row][c4 + 1] = v.y * SCALE;
        Qs[row][c4 + 2] = v.z * SCALE;
        Qs[row][c4 + 3] = v.w * SCALE;
    }

    float o[4][8];
#pragma unroll
    for (int i = 0; i < 4; i++)
#pragma unroll
        for (int j = 0; j < 8; j++) o[i][j] = 0.f;
    float mr[4] = {-INFINITY, -INFINITY, -INFINITY, -INFINITY};
    float lr[4] = {0.f, 0.f, 0.f, 0.f};

    for (int kt = 0; kt <= qt; kt++) {
        __syncthreads();
        const float* Kg = g_k + base + (size_t)kt * 64 * NHD;
        const float* Vg = g_v + base + (size_t)kt * 64 * NHD;
#pragma unroll
        for (int it = 0; it < 8; it++) {
            const int f4  = t + it * 128;
            const int row = f4 >> 4;
            const int c4  = (f4 & 15) << 2;
            float4 kv4 = *(const float4*)(Kg + row * NHD + c4);
            float4 vv4 = *(const float4*)(Vg + row * NHD + c4);
            Ks[row][c4 + 0] = kv4.x; Ks[row][c4 + 1] = kv4.y;
            Ks[row][c4 + 2] = kv4.z; Ks[row][c4 + 3] = kv4.w;
            Vs[row][c4 + 0] = vv4.x; Vs[row][c4 + 1] = vv4.y;
            Vs[row][c4 + 2] = vv4.z; Vs[row][c4 + 3] = vv4.w;
        }
        __syncthreads();

        float s[4][8];
#pragma unroll
        for (int i = 0; i < 4; i++)
#pragma unroll
            for (int j = 0; j < 8; j++) s[i][j] = 0.f;

#pragma unroll 8
        for (int d = 0; d < 64; d++) {
            float kv[8];
#pragma unroll
            for (int j = 0; j < 8; j++) kv[j] = Ks[cg + (j << 3)][d];
#pragma unroll
            for (int i = 0; i < 4; i++) {
                const float qv = Qs[(rg << 2) + i][d];
#pragma unroll
                for (int j = 0; j < 8; j++)
                    s[i][j] = fmaf(qv, kv[j], s[i][j]);
            }
        }

        if (kt == qt) {
#pragma unroll
            for (int i = 0; i < 4; i++)
#pragma unroll
                for (int j = 0; j < 8; j++)
                    if (cg + (j << 3) > (rg << 2) + i) s[i][j] = -INFINITY;
        }

#pragma unroll
        for (int i = 0; i < 4; i++) {
            float tm = s[i][0];
#pragma unroll
            for (int j = 1; j < 8; j++) tm = fmaxf(tm, s[i][j]);
            tm = fmaxf(tm, __shfl_xor_sync(0xffffffffu, tm, 1));
            tm = fmaxf(tm, __shfl_xor_sync(0xffffffffu, tm, 2));
            tm = fmaxf(tm, __shfl_xor_sync(0xffffffffu, tm, 4));
            const float nm   = fmaxf(mr[i], tm);
            const float corr = __expf(mr[i] - nm);
            mr[i] = nm;
            float ls = 0.f;
#pragma unroll
            for (int j = 0; j < 8; j++) {
                const float p = __expf(s[i][j] - nm);
                s[i][j] = p;
                ls += p;
            }
            ls += __shfl_xor_sync(0xffffffffu, ls, 1);
            ls += __shfl_xor_sync(0xffffffffu, ls, 2);
            ls += __shfl_xor_sync(0xffffffffu, ls, 4);
            lr[i] = lr[i] * corr + ls;
#pragma unroll
            for (int j = 0; j < 8; j++) o[i][j] *= corr;
        }

#pragma unroll
        for (int i = 0; i < 4; i++)
#pragma unroll
            for (int j = 0; j < 8; j++)
                Ps[(rg << 2) + i][cg + (j << 3)] = s[i][j];
        __syncthreads();

#pragma unroll 8
        for (int c = 0; c < 64; c++) {
            float vv[8];
#pragma unroll
            for (int j = 0; j < 8; j++) vv[j] = Vs[c][cg + (j << 3)];
#pragma unroll
            for (int i = 0; i < 4; i++) {
                const float p = Ps[(rg << 2) + i][c];
#pragma unroll
                for (int j = 0; j < 8; j++)
                    o[i][j] = fmaf(p, vv[j], o[i][j]);
            }
        }
    }

    const int b = bh >> 4;
    const int h = bh & (NH - 1);
#pragma unroll
    for (int i = 0; i < 4; i++) {
        const float inv  = 1.0f / lr[i];
        const int   srow = qt * 64 + (rg << 2) + i;
        float* dst = g_attn + ((size_t)(b * NS + srow)) * ND + h * NHD;
#pragma unroll
        for (int j = 0; j < 8; j++)
            dst[cg + (j << 3)] = o[i][j] * inv;
    }
}

// ---------------------------------------------------------------------------
// kernel_launch
// ---------------------------------------------------------------------------
extern "C" void kernel_launch(void* const* d_in, const int* in_sizes, int n_in,
                              void* d_out, int out_size)
{
    (void)in_sizes; (void)n_in; (void)out_size;
    const float* x     = (const float*)d_in[0];
    const float* Wqkv  = (const float*)d_in[1];
    const float* bqkv  = (const float*)d_in[2];
    const float* Wproj = (const float*)d_in[3];
    const float* bproj = (const float*)d_in[4];
    float* out = (float*)d_out;

    void *p_ahi, *p_alo, *p_wqh, *p_wql, *p_wph, *p_wpl, *p_attn;
    cudaGetSymbolAddress(&p_ahi, g_ahi);
    cudaGetSymbolAddress(&p_alo, g_alo);
    cudaGetSymbolAddress(&p_wqh, g_wqh);
    cudaGetSymbolAddress(&p_wql, g_wql);
    cudaGetSymbolAddress(&p_wph, g_wph);
    cudaGetSymbolAddress(&p_wpl, g_wpl);
    cudaGetSymbolAddress(&p_attn, g_attn);
    float* ahi = (float*)p_ahi; float* alo = (float*)p_alo;
    float* wqh = (float*)p_wqh; float* wql = (float*)p_wql;
    float* wph = (float*)p_wph; float* wpl = (float*)p_wpl;
    float* attn = (float*)p_attn;

    static bool attr_done = false;
    if (!attr_done) {
        cudaFuncSetAttribute((const void*)gemm_mma<0>,
                             cudaFuncAttributeMaxDynamicSharedMemorySize, GEMM_SMEM);
        cudaFuncSetAttribute((const void*)gemm_mma<1>,
                             cudaFuncAttributeMaxDynamicSharedMemorySize, GEMM_SMEM);
        cudaFuncSetAttribute((const void*)attn64,
                             cudaFuncAttributeMaxDynamicSharedMemorySize, ATTN_SMEM);
        attr_done = true;
    }

    // 0) weight transpose+split
    {
        dim3 b(32, 8);
        tsplit_kernel<<<dim3(3 * ND / 32, ND / 32), b>>>(Wqkv, wqh, wql, ND, 3 * ND);
        tsplit_kernel<<<dim3(ND / 32, ND / 32), b>>>(Wproj, wph, wpl, ND, ND);
    }

    // 1) split x into hi/lo
    split_kernel<<<2048, 256>>>(x, ahi, alo, NB * NS * ND);

    // 2) QKV GEMM (3xTF32 mma.sync) -> scatter q/k/v with bias
    gemm_mma<0><<<dim3(3 * ND / 128, NB * NS / 128), 256, GEMM_SMEM>>>(
        ahi, alo, wqh, wql, bqkv, nullptr, NB * NS, 3 * ND, ND);

    // 3) causal flash attention -> g_attn [b,s,d]
    attn64<<<dim3(NS / 64, NB * NH), 128, ATTN_SMEM>>>();

    // 4) split attn into hi/lo (reuse ahi/alo)
    split_kernel<<<2048, 256>>>(attn, ahi, alo, NB * NS * ND);

    // 5) output projection (3xTF32 mma.sync) -> d_out with bias
    gemm_mma<1><<<dim3(ND / 128, NB * NS / 128), 256, GEMM_SMEM>>>(
        ahi, alo, wph, wpl, bproj, out, NB * NS, ND, ND);
}

// round 4
// speedup vs baseline: 1.5995x; 1.2176x over previous
#include <cuda_runtime.h>
#include <math.h>
#include <stdint.h>

// Problem constants
#define NB  2
#define NS  2048
#define ND  1024
#define NH  16
#define NHD 64
#define SCALE 0.125f   // 1/sqrt(64)

// ---------------------------------------------------------------------------
// Scratch (allocation-free contract: __device__ globals)
// ---------------------------------------------------------------------------
__device__ float g_qh[NB * NH * NS * NHD];     // [bh][s][hd]  (pre-scaled hi)
__device__ float g_ql[NB * NH * NS * NHD];
__device__ float g_kh[NB * NH * NS * NHD];     // [bh][s][hd]
__device__ float g_kl[NB * NH * NS * NHD];
__device__ float g_vh[NB * NH * NS * NHD];     // [bh][hd][s]  (transposed)
__device__ float g_vl[NB * NH * NS * NHD];
__device__ float g_ahi[NB * NS * ND];          // hi/lo split activations
__device__ float g_alo[NB * NS * ND];
__device__ float g_wqh[3 * ND * ND];           // W_qkv^T hi  [3072 x 1024]
__device__ float g_wql[3 * ND * ND];
__device__ float g_wph[ND * ND];               // W_proj^T hi [1024 x 1024]
__device__ float g_wpl[ND * ND];

// ---------------------------------------------------------------------------
// Helpers
// ---------------------------------------------------------------------------
__device__ __forceinline__ uint32_t smem_u32(const void* p) {
    uint32_t a;
    asm("{ .reg .u64 t; cvta.to.shared.u64 t, %1; cvt.u32.u64 %0, t; }"
        : "=r"(a) : "l"(p));
    return a;
}

__device__ __forceinline__ void cp_async16(uint32_t saddr, const void* gptr) {
    asm volatile("cp.async.cg.shared.global [%0], [%1], 16;" :: "r"(saddr), "l"(gptr));
}
#define CP_COMMIT() asm volatile("cp.async.commit_group;" ::: "memory")

__device__ __forceinline__ void split_tf32(float v, float& hi, float& lo) {
    uint32_t u;
    asm("cvt.rna.tf32.f32 %0, %1;" : "=r"(u) : "f"(v));
    hi = __uint_as_float(u);
    float r = v - hi;
    uint32_t u2;
    asm("cvt.rna.tf32.f32 %0, %1;" : "=r"(u2) : "f"(r));
    lo = __uint_as_float(u2);
}

__device__ __forceinline__ uint32_t to_tf32(float v) {
    uint32_t u;
    asm("cvt.rna.tf32.f32 %0, %1;" : "=r"(u) : "f"(v));
    return u;
}

// m16n8k8 tf32 MMA, fp32 accumulate in-place
__device__ __forceinline__ void mma_tf32(float* d, const uint32_t* a, const uint32_t* b) {
    asm volatile(
        "mma.sync.aligned.m16n8k8.row.col.f32.tf32.tf32.f32 "
        "{%0,%1,%2,%3}, {%4,%5,%6,%7}, {%8,%9}, {%0,%1,%2,%3};"
        : "+f"(d[0]), "+f"(d[1]), "+f"(d[2]), "+f"(d[3])
        : "r"(a[0]), "r"(a[1]), "r"(a[2]), "r"(a[3]), "r"(b[0]), "r"(b[1]));
}

// FFMA-only exp (x <= 0 expected; handles -inf via clamp). rel err ~2.4e-6.
__device__ __forceinline__ float fexp(float x) {
    x = fmaxf(x, -60.0f);
    const float y = x * 1.44269504f;
    const float t = y + 12582912.0f;              // 1.5 * 2^23
    const int   n = __float_as_int(t) - 0x4B400000;
    const float f = y - (t - 12582912.0f);        // [-0.5, 0.5]
    float p = 1.33335581e-3f;
    p = fmaf(p, f, 9.61812910e-3f);
    p = fmaf(p, f, 5.55041087e-2f);
    p = fmaf(p, f, 2.40226510e-1f);
    p = fmaf(p, f, 6.93147182e-1f);
    p = fmaf(p, f, 1.0f);
    return __int_as_float(__float_as_int(p) + (n << 23));
}

// ---------------------------------------------------------------------------
// Prep kernels
// ---------------------------------------------------------------------------
__global__ void split_kernel(const float* __restrict__ in,
                             float* __restrict__ hi, float* __restrict__ lo, int n) {
    for (int i = blockIdx.x * blockDim.x + threadIdx.x; i < n; i += gridDim.x * blockDim.x) {
        float h, l;
        split_tf32(in[i], h, l);
        hi[i] = h;
        lo[i] = l;
    }
}

// W [K,N] row-major  ->  T [N,K] row-major (hi/lo split)
__global__ __launch_bounds__(256) void tsplit_kernel(
    const float* __restrict__ W, float* __restrict__ Thi, float* __restrict__ Tlo,
    int K, int N) {
    __shared__ float tile[32][33];
    const int tx = threadIdx.x;
    const int ty = threadIdx.y;
    const int n0 = blockIdx.x * 32;
    const int k0 = blockIdx.y * 32;
#pragma unroll
    for (int i = 0; i < 32; i += 8)
        tile[ty + i][tx] = W[(size_t)(k0 + ty + i) * N + n0 + tx];
    __syncthreads();
#pragma unroll
    for (int i = 0; i < 32; i += 8) {
        float v = tile[tx][ty + i];
        float h, l;
        split_tf32(v, h, l);
        Thi[(size_t)(n0 + ty + i) * K + k0 + tx] = h;
        Tlo[(size_t)(n0 + ty + i) * K + k0 + tx] = l;
    }
}

// ---------------------------------------------------------------------------
// 3xTF32 mma.sync GEMM: C[M,N] = A[M,K] * B[N,K]^T
// 128x128 tile/CTA, 256 threads, warps 2(m) x 4(n), warp tile 64x32.
// MODE 0: split-scatter QKV (q scaled+split, k split, v split+transposed)
// MODE 1: C = acc + bias
// ---------------------------------------------------------------------------
#define KC     32
#define APAD   4
#define ROWF   (KC + APAD)
#define TILEF  (128 * ROWF)
#define STAGEF (4 * TILEF)
#define GEMM_SMEM (2 * STAGEF * 4)

template <int MODE>
__global__ __launch_bounds__(256, 1) void gemm_mma(
    const float* __restrict__ Ahi, const float* __restrict__ Alo,
    const float* __restrict__ Bhi, const float* __restrict__ Blo,
    const float* __restrict__ bias, float* __restrict__ C,
    int M, int N, int K)
{
    extern __shared__ float smf[];
    const int tid  = threadIdx.x;
    const int lane = tid & 31;
    const int wid  = tid >> 5;
    const int wm   = wid >> 2;
    const int wn   = wid & 3;
    const int g    = lane >> 2;
    const int tg   = lane & 3;
    const int bm = blockIdx.y * 128;
    const int bn = blockIdx.x * 128;

    const float* srcT[4] = {Ahi, Alo, Bhi, Blo};

    auto load_stage = [&](int c, int s) {
        const int k0 = c * KC;
        float* stage = smf + s * STAGEF;
#pragma unroll
        for (int t = 0; t < 4; t++) {
            const float* src = srcT[t];
            const int rbase = (t < 2) ? bm : bn;
            float* dst = stage + t * TILEF;
#pragma unroll
            for (int i = 0; i < 4; i++) {
                const int idx = tid + i * 256;
                const int r = idx >> 3;
                const int q = idx & 7;
                const float* gp = src + (size_t)(rbase + r) * K + k0 + q * 4;
                cp_async16(smem_u32(dst + r * ROWF + q * 4), gp);
            }
        }
        CP_COMMIT();
    };

    float acc[4][4][4];
#pragma unroll
    for (int i = 0; i < 4; i++)
#pragma unroll
        for (int j = 0; j < 4; j++)
#pragma unroll
            for (int kq = 0; kq < 4; kq++) acc[i][j][kq] = 0.f;

    const int NCH = K / KC;
    load_stage(0, 0);

    for (int c = 0; c < NCH; c++) {
        const int s = c & 1;
        if (c + 1 < NCH) {
            load_stage(c + 1, (c + 1) & 1);
            asm volatile("cp.async.wait_group 1;" ::: "memory");
        } else {
            asm volatile("cp.async.wait_group 0;" ::: "memory");
        }
        __syncthreads();

        const float* Ah = smf + s * STAGEF;
        const float* Al = Ah + TILEF;
        const float* Bh = Ah + 2 * TILEF;
        const float* Bl = Ah + 3 * TILEF;

#pragma unroll
        for (int ks = 0; ks < 4; ks++) {
            const int kb = ks * 8;
            uint32_t ah[4][4], al[4][4], bh[4][2], bl[4][2];
#pragma unroll
            for (int am = 0; am < 4; am++) {
                const int r0 = wm * 64 + am * 16 + g;
                ah[am][0] = __float_as_uint(Ah[(r0    ) * ROWF + kb + tg    ]);
                ah[am][1] = __float_as_uint(Ah[(r0 + 8) * ROWF + kb + tg    ]);
                ah[am][2] = __float_as_uint(Ah[(r0    ) * ROWF + kb + tg + 4]);
                ah[am][3] = __float_as_uint(Ah[(r0 + 8) * ROWF + kb + tg + 4]);
                al[am][0] = __float_as_uint(Al[(r0    ) * ROWF + kb + tg    ]);
                al[am][1] = __float_as_uint(Al[(r0 + 8) * ROWF + kb + tg    ]);
                al[am][2] = __float_as_uint(Al[(r0    ) * ROWF + kb + tg + 4]);
                al[am][3] = __float_as_uint(Al[(r0 + 8) * ROWF + kb + tg + 4]);
            }
#pragma unroll
            for (int an = 0; an < 4; an++) {
                const int n0 = wn * 32 + an * 8 + g;
                bh[an][0] = __float_as_uint(Bh[n0 * ROWF + kb + tg    ]);
                bh[an][1] = __float_as_uint(Bh[n0 * ROWF + kb + tg + 4]);
                bl[an][0] = __float_as_uint(Bl[n0 * ROWF + kb + tg    ]);
                bl[an][1] = __float_as_uint(Bl[n0 * ROWF + kb + tg + 4]);
            }
            // pass-outer ordering: 16 independent MMAs between accumulator reuse
#pragma unroll
            for (int am = 0; am < 4; am++)
#pragma unroll
                for (int an = 0; an < 4; an++)
                    mma_tf32(acc[am][an], ah[am], bh[an]);
#pragma unroll
            for (int am = 0; am < 4; am++)
#pragma unroll
                for (int an = 0; an < 4; an++)
                    mma_tf32(acc[am][an], ah[am], bl[an]);
#pragma unroll
            for (int am = 0; am < 4; am++)
#pragma unroll
                for (int an = 0; an < 4; an++)
                    mma_tf32(acc[am][an], al[am], bh[an]);
        }
        __syncthreads();
    }

    // ---- epilogue ----
#pragma unroll
    for (int am = 0; am < 4; am++) {
        const int row0 = bm + wm * 64 + am * 16 + g;
#pragma unroll
        for (int an = 0; an < 4; an++) {
            const int col = bn + wn * 32 + an * 8 + 2 * tg;
            const float v00 = acc[am][an][0] + bias[col];
            const float v01 = acc[am][an][1] + bias[col + 1];
            const float v10 = acc[am][an][2] + bias[col];
            const float v11 = acc[am][an][3] + bias[col + 1];
            if (MODE == 0) {
#pragma unroll
                for (int e = 0; e < 4; e++) {
                    const int m = (e < 2) ? row0 : row0 + 8;
                    const int n = col + (e & 1);
                    const float v = (e == 0) ? v00 : (e == 1) ? v01 : (e == 2) ? v10 : v11;
                    const int b = m >> 11;            // NS = 2048
                    const int srow = m & (NS - 1);
                    const int which = n >> 10;        // ND = 1024
                    const int dcol  = n & (ND - 1);
                    const int h  = dcol >> 6;         // NHD = 64
                    const int hd = dcol & 63;
                    const int bhh = b * NH + h;
                    float hi, lo;
                    if (which == 0) {
                        split_tf32(v * SCALE, hi, lo);
                        const size_t o = ((size_t)bhh * NS + srow) * NHD + hd;
                        g_qh[o] = hi; g_ql[o] = lo;
                    } else if (which == 1) {
                        split_tf32(v, hi, lo);
                        const size_t o = ((size_t)bhh * NS + srow) * NHD + hd;
                        g_kh[o] = hi; g_kl[o] = lo;
                    } else {
                        split_tf32(v, hi, lo);
                        const size_t o = ((size_t)bhh * NHD + hd) * NS + srow;
                        g_vh[o] = hi; g_vl[o] = lo;
                    }
                }
            } else {
                *(float2*)(C + (size_t)row0 * N + col)       = make_float2(v00, v01);
                *(float2*)(C + (size_t)(row0 + 8) * N + col) = make_float2(v10, v11);
            }
        }
    }
}

// ---------------------------------------------------------------------------
// Tensor-core causal flash attention.
// CTA: 128 q rows x (KV tiles of 64), 256 threads = 8 warps, warp = m16 band.
// QK^T: 3xTF32; PV: 2 passes (P->tf32 x Vh, x Vl). FFMA softmax exp.
// Output written hi/lo-split directly into g_ahi/g_alo ([b,s,d]).
// Smem: 2-stage KV ring (Kh,Kl,Vh,Vl 64x68 each) + P (128x68).
// ---------------------------------------------------------------------------
#define AST   68
#define STG_F (4 * 64 * AST)
#define P_OFF (2 * STG_F)
#define ATTN_SMEM ((2 * STG_F + 128 * AST) * 4)

__global__ __launch_bounds__(256, 1) void attn_mma()
{
    extern __shared__ float smf[];
    const int tid  = threadIdx.x;
    const int lane = tid & 31;
    const int w    = tid >> 5;
    const int g    = lane >> 2;
    const int tg   = lane & 3;
    const int qt   = 15 - blockIdx.x;      // heavy CTAs first
    const int bh   = blockIdx.y;
    const int qbase = qt * 128;

    const float* Qh = g_qh + (size_t)bh * NS * NHD;
    const float* Ql = g_ql + (size_t)bh * NS * NHD;
    const float* Kh = g_kh + (size_t)bh * NS * NHD;
    const float* Kl = g_kl + (size_t)bh * NS * NHD;
    const float* Vh = g_vh + (size_t)bh * NHD * NS;
    const float* Vl = g_vl + (size_t)bh * NHD * NS;

    const int r0 = qbase + w * 16 + g;     // global q row of accum row 0

    // Q fragments resident in registers for the whole CTA
    float qfh[8][4], qfl[8][4];
#pragma unroll
    for (int ks = 0; ks < 8; ks++) {
        const int kb = ks * 8;
        qfh[ks][0] = Qh[(size_t)r0 * NHD + kb + tg];
        qfh[ks][1] = Qh[(size_t)(r0 + 8) * NHD + kb + tg];
        qfh[ks][2] = Qh[(size_t)r0 * NHD + kb + tg + 4];
        qfh[ks][3] = Qh[(size_t)(r0 + 8) * NHD + kb + tg + 4];
        qfl[ks][0] = Ql[(size_t)r0 * NHD + kb + tg];
        qfl[ks][1] = Ql[(size_t)(r0 + 8) * NHD + kb + tg];
        qfl[ks][2] = Ql[(size_t)r0 * NHD + kb + tg + 4];
        qfl[ks][3] = Ql[(size_t)(r0 + 8) * NHD + kb + tg + 4];
    }

    float o[8][4];
#pragma unroll
    for (int j = 0; j < 8; j++)
#pragma unroll
        for (int c = 0; c < 4; c++) o[j][c] = 0.f;
    float m[2] = {-INFINITY, -INFINITY};
    float l[2] = {0.f, 0.f};

    const int nt = 2 * qt + 2;

    auto load_tile = [&](int kt, int s) {
        float* st = smf + s * STG_F;
#pragma unroll
        for (int i = 0; i < 4; i++) {
            const int idx = tid + i * 256;       // 0..1023
            const int row = idx >> 4;            // 0..63
            const int q4  = (idx & 15) << 2;     // 0..60
            const uint32_t d = smem_u32(st + row * AST + q4);
            cp_async16(d,                     Kh + (size_t)(kt * 64 + row) * NHD + q4);
            cp_async16(d + 64 * AST * 4,      Kl + (size_t)(kt * 64 + row) * NHD + q4);
            cp_async16(d + 2 * 64 * AST * 4,  Vh + (size_t)row * NS + kt * 64 + q4);
            cp_async16(d + 3 * 64 * AST * 4,  Vl + (size_t)row * NS + kt * 64 + q4);
        }
        CP_COMMIT();
    };

    load_tile(0, 0);

    for (int kt = 0; kt < nt; kt++) {
        const int s = kt & 1;
        __syncthreads();                        // all warps done with stage s^1
        if (kt + 1 < nt) {
            load_tile(kt + 1, s ^ 1);
            asm volatile("cp.async.wait_group 1;" ::: "memory");
        } else {
            asm volatile("cp.async.wait_group 0;" ::: "memory");
        }
        __syncthreads();                        // stage s visible to all

        const float* sKh = smf + s * STG_F;
        const float* sKl = sKh + 64 * AST;
        const float* sVh = sKh + 2 * 64 * AST;
        const float* sVl = sKh + 3 * 64 * AST;

        // ---- S = Q K^T (3xTF32) ----
        float sc[8][4];
#pragma unroll
        for (int j = 0; j < 8; j++)
#pragma unroll
            for (int c = 0; c < 4; c++) sc[j][c] = 0.f;

#pragma unroll
        for (int ks = 0; ks < 8; ks++) {
            const int kb = ks * 8;
            uint32_t bfh[8][2], bfl[8][2];
#pragma unroll
            for (int j = 0; j < 8; j++) {
                const int n0 = j * 8 + g;
                bfh[j][0] = __float_as_uint(sKh[n0 * AST + kb + tg    ]);
                bfh[j][1] = __float_as_uint(sKh[n0 * AST + kb + tg + 4]);
                bfl[j][0] = __float_as_uint(sKl[n0 * AST + kb + tg    ]);
                bfl[j][1] = __float_as_uint(sKl[n0 * AST + kb + tg + 4]);
            }
            uint32_t ah[4], al[4];
#pragma unroll
            for (int i = 0; i < 4; i++) {
                ah[i] = __float_as_uint(qfh[ks][i]);
                al[i] = __float_as_uint(qfl[ks][i]);
            }
#pragma unroll
            for (int j = 0; j < 8; j++) mma_tf32(sc[j], ah, bfh[j]);
#pragma unroll
            for (int j = 0; j < 8; j++) mma_tf32(sc[j], ah, bfl[j]);
#pragma unroll
            for (int j = 0; j < 8; j++) mma_tf32(sc[j], al, bfh[j]);
        }

        // ---- causal mask (only the two diagonal tiles) ----
        if (kt >= 2 * qt) {
            const int colb = kt * 64;
#pragma unroll
            for (int j = 0; j < 8; j++) {
                const int c0 = colb + j * 8 + 2 * tg;
#pragma unroll
                for (int c = 0; c < 4; c++) {
                    const int col = c0 + (c & 1);
                    const int row = (c < 2) ? r0 : r0 + 8;
                    if (col > row) sc[j][c] = -INFINITY;
                }
            }
        }

        // ---- online softmax (FFMA exp) ----
#pragma unroll
        for (int r = 0; r < 2; r++) {
            float rm = -INFINITY;
#pragma unroll
            for (int j = 0; j < 8; j++)
                rm = fmaxf(rm, fmaxf(sc[j][2 * r], sc[j][2 * r + 1]));
            rm = fmaxf(rm, __shfl_xor_sync(0xffffffffu, rm, 1));
            rm = fmaxf(rm, __shfl_xor_sync(0xffffffffu, rm, 2));
            const float mn   = fmaxf(m[r], rm);
            const float corr = fexp(m[r] - mn);
            m[r] = mn;
            float ps = 0.f;
#pragma unroll
            for (int j = 0; j < 8; j++) {
                const float p0 = fexp(sc[j][2 * r]     - mn);
                const float p1 = fexp(sc[j][2 * r + 1] - mn);
                sc[j][2 * r]     = p0;
                sc[j][2 * r + 1] = p1;
                ps += p0 + p1;
            }
            l[r] = l[r] * corr + ps;
#pragma unroll
            for (int j = 0; j < 8; j++) {
                o[j][2 * r]     *= corr;
                o[j][2 * r + 1] *= corr;
            }
        }

        // ---- stage P (per-warp private band) ----
        {
            float* Pp = smf + P_OFF;
            const int pr = w * 16 + g;
#pragma unroll
            for (int j = 0; j < 8; j++) {
                *(float2*)&Pp[(pr    ) * AST + j * 8 + 2 * tg] = make_float2(sc[j][0], sc[j][1]);
                *(float2*)&Pp[(pr + 8) * AST + j * 8 + 2 * tg] = make_float2(sc[j][2], sc[j][3]);
            }
        }
        __syncwarp();

        // ---- O += P V  (2 passes: Ph*Vh + Ph*Vl) ----
        {
            const float* Pp = smf + P_OFF;
            const int pr = w * 16 + g;
#pragma unroll
            for (int ks = 0; ks < 8; ks++) {
                const int kb = ks * 8;
                uint32_t pa[4];
                pa[0] = to_tf32(Pp[(pr    ) * AST + kb + tg    ]);
                pa[1] = to_tf32(Pp[(pr + 8) * AST + kb + tg    ]);
                pa[2] = to_tf32(Pp[(pr    ) * AST + kb + tg + 4]);
                pa[3] = to_tf32(Pp[(pr + 8) * AST + kb + tg + 4]);
                uint32_t vfh[8][2], vfl[8][2];
#pragma unroll
                for (int j = 0; j < 8; j++) {
                    const int n0 = j * 8 + g;
                    vfh[j][0] = __float_as_uint(sVh[n0 * AST + kb + tg    ]);
                    vfh[j][1] = __float_as_uint(sVh[n0 * AST + kb + tg + 4]);
                    vfl[j][0] = __float_as_uint(sVl[n0 * AST + kb + tg    ]);
                    vfl[j][1] = __float_as_uint(sVl[n0 * AST + kb + tg + 4]);
                }
#pragma unroll
                for (int j = 0; j < 8; j++) mma_tf32(o[j], pa, vfh[j]);
#pragma unroll
                for (int j = 0; j < 8; j++) mma_tf32(o[j], pa, vfl[j]);
            }
        }
    }

    // ---- finalize: normalize, split, write to g_ahi/g_alo ----
#pragma unroll
    for (int r = 0; r < 2; r++) {
        float lv = l[r];
        lv += __shfl_xor_sync(0xffffffffu, lv, 1);
        lv += __shfl_xor_sync(0xffffffffu, lv, 2);
        l[r] = 1.0f / lv;
    }
    const int b = bh >> 4;
    const int h = bh & (NH - 1);
#pragma unroll
    for (int j = 0; j < 8; j++) {
        const int col = h * NHD + j * 8 + 2 * tg;
#pragma unroll
        for (int r = 0; r < 2; r++) {
            const int row = (r == 0) ? r0 : r0 + 8;
            const size_t off = ((size_t)(b * NS) + row) * ND + col;
            const float v0 = o[j][2 * r]     * l[r];
            const float v1 = o[j][2 * r + 1] * l[r];
            float h0, l0, h1, l1;
            split_tf32(v0, h0, l0);
            split_tf32(v1, h1, l1);
            *(float2*)(g_ahi + off) = make_float2(h0, h1);
            *(float2*)(g_alo + off) = make_float2(l0, l1);
        }
    }
}

// ---------------------------------------------------------------------------
// kernel_launch
// ---------------------------------------------------------------------------
extern "C" void kernel_launch(void* const* d_in, const int* in_sizes, int n_in,
                              void* d_out, int out_size)
{
    (void)in_sizes; (void)n_in; (void)out_size;
    const float* x     = (const float*)d_in[0];
    const float* Wqkv  = (const float*)d_in[1];
    const float* bqkv  = (const float*)d_in[2];
    const float* Wproj = (const float*)d_in[3];
    const float* bproj = (const float*)d_in[4];
    float* out = (float*)d_out;

    void *p_ahi, *p_alo, *p_wqh, *p_wql, *p_wph, *p_wpl;
    cudaGetSymbolAddress(&p_ahi, g_ahi);
    cudaGetSymbolAddress(&p_alo, g_alo);
    cudaGetSymbolAddress(&p_wqh, g_wqh);
    cudaGetSymbolAddress(&p_wql, g_wql);
    cudaGetSymbolAddress(&p_wph, g_wph);
    cudaGetSymbolAddress(&p_wpl, g_wpl);
    float* ahi = (float*)p_ahi; float* alo = (float*)p_alo;
    float* wqh = (float*)p_wqh; float* wql = (float*)p_wql;
    float* wph = (float*)p_wph; float* wpl = (float*)p_wpl;

    static bool attr_done = false;
    if (!attr_done) {
        cudaFuncSetAttribute((const void*)gemm_mma<0>,
                             cudaFuncAttributeMaxDynamicSharedMemorySize, GEMM_SMEM);
        cudaFuncSetAttribute((const void*)gemm_mma<1>,
                             cudaFuncAttributeMaxDynamicSharedMemorySize, GEMM_SMEM);
        cudaFuncSetAttribute((const void*)attn_mma,
                             cudaFuncAttributeMaxDynamicSharedMemorySize, ATTN_SMEM);
        attr_done = true;
    }

    // 0) weight transpose+split
    {
        dim3 b(32, 8);
        tsplit_kernel<<<dim3(3 * ND / 32, ND / 32), b>>>(Wqkv, wqh, wql, ND, 3 * ND);
        tsplit_kernel<<<dim3(ND / 32, ND / 32), b>>>(Wproj, wph, wpl, ND, ND);
    }

    // 1) split x into hi/lo
    split_kernel<<<2048, 256>>>(x, ahi, alo, NB * NS * ND);

    // 2) QKV GEMM -> split-scatter q/k/v (v transposed) with bias
    gemm_mma<0><<<dim3(3 * ND / 128, NB * NS / 128), 256, GEMM_SMEM>>>(
        ahi, alo, wqh, wql, bqkv, nullptr, NB * NS, 3 * ND, ND);

    // 3) tensor-core causal flash attention -> g_ahi/g_alo (pre-split)
    attn_mma<<<dim3(NS / 128, NB * NH), 256, ATTN_SMEM>>>();

    // 4) output projection -> d_out with bias
    gemm_mma<1><<<dim3(ND / 128, NB * NS / 128), 256, GEMM_SMEM>>>(
        ahi, alo, wph, wpl, bproj, out, NB * NS, ND, ND);
}

// round 6
// speedup vs baseline: 2.8587x; 1.7873x over previous
#include <cuda_runtime.h>
#include <cuda_fp16.h>
#include <math.h>
#include <stdint.h>

// Problem constants
#define NB  2
#define NS  2048
#define ND  1024
#define NH  16
#define NHD 64
#define SCALE  0.125f    // 1/sqrt(64), applied to scores post-MMA
#define WSCALE 32.0f     // weight pre-scale (keeps w_lo out of fp16 subnormals)
#define INVW   0.03125f

// ---------------------------------------------------------------------------
// Scratch (allocation-free contract: __device__ globals)
// ---------------------------------------------------------------------------
__device__ __half g_qh[NB * NH * NS * NHD];   // [bh][s][hd]  (unscaled hi)
__device__ __half g_ql[NB * NH * NS * NHD];
__device__ __half g_kh[NB * NH * NS * NHD];   // [bh][s][hd]
__device__ __half g_kl[NB * NH * NS * NHD];
__device__ __half g_vh[NB * NH * NS * NHD];   // [bh][hd][s]  (transposed)
__device__ __half g_vl[NB * NH * NS * NHD];
__device__ __half g_axh[NB * NS * ND];        // activation hi/lo (x, then attn out)
__device__ __half g_axl[NB * NS * ND];
__device__ __half g_wqh[3 * ND * ND];         // W_qkv^T * 32, hi   [3072 x 1024]
__device__ __half g_wql[3 * ND * ND];
__device__ __half g_wph[ND * ND];             // W_proj^T * 32, hi  [1024 x 1024]
__device__ __half g_wpl[ND * ND];

// ---------------------------------------------------------------------------
// Helpers
// ---------------------------------------------------------------------------
__device__ __forceinline__ uint32_t smem_u32(const void* p) {
    uint32_t a;
    asm("{ .reg .u64 t; cvta.to.shared.u64 t, %1; cvt.u32.u64 %0, t; }"
        : "=r"(a) : "l"(p));
    return a;
}

__device__ __forceinline__ void cp_async16(uint32_t saddr, const void* gptr) {
    asm volatile("cp.async.cg.shared.global [%0], [%1], 16;" :: "r"(saddr), "l"(gptr));
}
#define CP_COMMIT() asm volatile("cp.async.commit_group;" ::: "memory")

__device__ __forceinline__ uint32_t ldh2(const __half* p) {
    return *reinterpret_cast<const uint32_t*>(p);
}

__device__ __forceinline__ uint32_t pack_h2(float a, float b) {
    __half2 h = __floats2half2_rn(a, b);
    return *reinterpret_cast<uint32_t*>(&h);
}

__device__ __forceinline__ void split_h(float v, __half& hi, __half& lo) {
    hi = __float2half_rn(v);
    lo = __float2half_rn(v - __half2float(hi));
}

// m16n8k16 f16 MMA, fp32 accumulate in-place
__device__ __forceinline__ void mma_f16(float* d, const uint32_t* a, const uint32_t* b) {
    asm volatile(
        "mma.sync.aligned.m16n8k16.row.col.f32.f16.f16.f32 "
        "{%0,%1,%2,%3}, {%4,%5,%6,%7}, {%8,%9}, {%0,%1,%2,%3};"
        : "+f"(d[0]), "+f"(d[1]), "+f"(d[2]), "+f"(d[3])
        : "r"(a[0]), "r"(a[1]), "r"(a[2]), "r"(a[3]), "r"(b[0]), "r"(b[1]));
}

// FFMA-only exp (finite x; clamp handles big negatives). rel err ~2.4e-6.
__device__ __forceinline__ float fexp(float x) {
    x = fmaxf(x, -60.0f);
    const float y = x * 1.44269504f;
    const float t = y + 12582912.0f;              // 1.5 * 2^23
    const int   n = __float_as_int(t) - 0x4B400000;
    const float f = y - (t - 12582912.0f);
    float p = 1.33335581e-3f;
    p = fmaf(p, f, 9.61812910e-3f);
    p = fmaf(p, f, 5.55041087e-2f);
    p = fmaf(p, f, 2.40226510e-1f);
    p = fmaf(p, f, 6.93147182e-1f);
    p = fmaf(p, f, 1.0f);
    return __int_as_float(__float_as_int(p) + (n << 23));
}

// ---------------------------------------------------------------------------
// Prep kernels
// ---------------------------------------------------------------------------
__global__ void split16_kernel(const float* __restrict__ in,
                               __half* __restrict__ hi, __half* __restrict__ lo, int n) {
    for (int i = blockIdx.x * blockDim.x + threadIdx.x; i < n; i += gridDim.x * blockDim.x) {
        __half h, l;
        split_h(in[i], h, l);
        hi[i] = h;
        lo[i] = l;
    }
}

// W [K,N] row-major -> T [N,K] row-major, scaled by WSCALE, fp16 hi/lo split
__global__ __launch_bounds__(256) void tsplit16_kernel(
    const float* __restrict__ W, __half* __restrict__ Thi, __half* __restrict__ Tlo,
    int K, int N) {
    __shared__ float tile[32][33];
    const int tx = threadIdx.x;
    const int ty = threadIdx.y;
    const int n0 = blockIdx.x * 32;
    const int k0 = blockIdx.y * 32;
#pragma unroll
    for (int i = 0; i < 32; i += 8)
        tile[ty + i][tx] = W[(size_t)(k0 + ty + i) * N + n0 + tx];
    __syncthreads();
#pragma unroll
    for (int i = 0; i < 32; i += 8) {
        float v = tile[tx][ty + i] * WSCALE;
        __half h, l;
        split_h(v, h, l);
        Thi[(size_t)(n0 + ty + i) * K + k0 + tx] = h;
        Tlo[(size_t)(n0 + ty + i) * K + k0 + tx] = l;
    }
}

// ---------------------------------------------------------------------------
// FP16x2 (3-pass) mma.sync GEMM: C[M,N] = (A[M,K] * B[N,K]^T) / 32
// 128x128 tile/CTA, 256 threads, warps 2(m) x 4(n), warp tile 64x32.
// K-chunk 64, double-buffered cp.async. fp32 accum.
// MODE 0: split-scatter QKV (q/k [bh][s][hd], v transposed [bh][hd][s])
// MODE 1: C = acc/32 + bias (fp32)
// ---------------------------------------------------------------------------
#define KC     64
#define ROWH   72                       // 64 + 8 halves pad
#define TILEH  (128 * ROWH)             // halves per tile
#define STAGEH (4 * TILEH)              // Ah, Al, Bh, Bl
#define GEMM_SMEM (2 * STAGEH * 2)      // bytes = 147456

template <int MODE>
__global__ __launch_bounds__(256, 1) void gemm_f16(
    const __half* __restrict__ Ahi, const __half* __restrict__ Alo,
    const __half* __restrict__ Bhi, const __half* __restrict__ Blo,
    const float* __restrict__ bias, float* __restrict__ C,
    int M, int N, int K)
{
    extern __shared__ __half smh[];
    const int tid  = threadIdx.x;
    const int lane = tid & 31;
    const int wid  = tid >> 5;
    const int wm   = wid >> 2;
    const int wn   = wid & 3;
    const int g    = lane >> 2;
    const int tg   = lane & 3;
    const int bm = blockIdx.y * 128;
    const int bn = blockIdx.x * 128;

    const __half* srcT[4] = {Ahi, Alo, Bhi, Blo};

    auto load_stage = [&](int c, int s) {
        const int k0 = c * KC;
        __half* stage = smh + s * STAGEH;
#pragma unroll
        for (int t = 0; t < 4; t++) {
            const __half* src = srcT[t];
            const int rbase = (t < 2) ? bm : bn;
            __half* dst = stage + t * TILEH;
#pragma unroll
            for (int i = 0; i < 4; i++) {
                const int idx = tid + i * 256;     // 0..1023
                const int r = idx >> 3;
                const int q = idx & 7;             // 8 halves (16B) per chunk
                cp_async16(smem_u32(dst + r * ROWH + q * 8),
                           src + (size_t)(rbase + r) * K + k0 + q * 8);
            }
        }
        CP_COMMIT();
    };

    float acc[4][4][4];
#pragma unroll
    for (int i = 0; i < 4; i++)
#pragma unroll
        for (int j = 0; j < 4; j++)
#pragma unroll
            for (int kq = 0; kq < 4; kq++) acc[i][j][kq] = 0.f;

    const int NCH = K / KC;
    load_stage(0, 0);

    for (int c = 0; c < NCH; c++) {
        const int s = c & 1;
        if (c + 1 < NCH) {
            load_stage(c + 1, (c + 1) & 1);
            asm volatile("cp.async.wait_group 1;" ::: "memory");
        } else {
            asm volatile("cp.async.wait_group 0;" ::: "memory");
        }
        __syncthreads();

        const __half* Ah = smh + s * STAGEH;
        const __half* Al = Ah + TILEH;
        const __half* Bh = Ah + 2 * TILEH;
        const __half* Bl = Ah + 3 * TILEH;

#pragma unroll
        for (int ks = 0; ks < 4; ks++) {
            const int kb = ks * 16;
            uint32_t ah[4][4], al[4][4], bh[4][2], bl[4][2];
#pragma unroll
            for (int am = 0; am < 4; am++) {
                const int r0 = wm * 64 + am * 16 + g;
                ah[am][0] = ldh2(Ah + (r0    ) * ROWH + kb + 2 * tg);
                ah[am][1] = ldh2(Ah + (r0 + 8) * ROWH + kb + 2 * tg);
                ah[am][2] = ldh2(Ah + (r0    ) * ROWH + kb + 8 + 2 * tg);
                ah[am][3] = ldh2(Ah + (r0 + 8) * ROWH + kb + 8 + 2 * tg);
                al[am][0] = ldh2(Al + (r0    ) * ROWH + kb + 2 * tg);
                al[am][1] = ldh2(Al + (r0 + 8) * ROWH + kb + 2 * tg);
                al[am][2] = ldh2(Al + (r0    ) * ROWH + kb + 8 + 2 * tg);
                al[am][3] = ldh2(Al + (r0 + 8) * ROWH + kb + 8 + 2 * tg);
            }
#pragma unroll
            for (int an = 0; an < 4; an++) {
                const int n0 = wn * 32 + an * 8 + g;
                bh[an][0] = ldh2(Bh + n0 * ROWH + kb + 2 * tg);
                bh[an][1] = ldh2(Bh + n0 * ROWH + kb + 8 + 2 * tg);
                bl[an][0] = ldh2(Bl + n0 * ROWH + kb + 2 * tg);
                bl[an][1] = ldh2(Bl + n0 * ROWH + kb + 8 + 2 * tg);
            }
#pragma unroll
            for (int am = 0; am < 4; am++)
#pragma unroll
                for (int an = 0; an < 4; an++)
                    mma_f16(acc[am][an], ah[am], bh[an]);
#pragma unroll
            for (int am = 0; am < 4; am++)
#pragma unroll
                for (int an = 0; an < 4; an++)
                    mma_f16(acc[am][an], ah[am], bl[an]);
#pragma unroll
            for (int am = 0; am < 4; am++)
#pragma unroll
                for (int an = 0; an < 4; an++)
                    mma_f16(acc[am][an], al[am], bh[an]);
        }
        __syncthreads();
    }

    // ---- epilogue ----
#pragma unroll
    for (int am = 0; am < 4; am++) {
        const int row0 = bm + wm * 64 + am * 16 + g;
#pragma unroll
        for (int an = 0; an < 4; an++) {
            const int col = bn + wn * 32 + an * 8 + 2 * tg;
            const float v00 = acc[am][an][0] * INVW + bias[col];
            const float v01 = acc[am][an][1] * INVW + bias[col + 1];
            const float v10 = acc[am][an][2] * INVW + bias[col];
            const float v11 = acc[am][an][3] * INVW + bias[col + 1];
            if (MODE == 0) {
#pragma unroll
                for (int e = 0; e < 4; e++) {
                    const int m = (e < 2) ? row0 : row0 + 8;
                    const int n = col + (e & 1);
                    const float v = (e == 0) ? v00 : (e == 1) ? v01 : (e == 2) ? v10 : v11;
                    const int b = m >> 11;            // NS = 2048
                    const int srow = m & (NS - 1);
                    const int which = n >> 10;        // ND = 1024
                    const int dcol  = n & (ND - 1);
                    const int h  = dcol >> 6;         // NHD = 64
                    const int hd = dcol & 63;
                    const int bhh = b * NH + h;
                    __half hi, lo;
                    split_h(v, hi, lo);
                    if (which == 0) {
                        const size_t o = ((size_t)bhh * NS + srow) * NHD + hd;
                        g_qh[o] = hi; g_ql[o] = lo;
                    } else if (which == 1) {
                        const size_t o = ((size_t)bhh * NS + srow) * NHD + hd;
                        g_kh[o] = hi; g_kl[o] = lo;
                    } else {
                        const size_t o = ((size_t)bhh * NHD + hd) * NS + srow;
                        g_vh[o] = hi; g_vl[o] = lo;
                    }
                }
            } else {
                *(float2*)(C + (size_t)row0 * N + col)       = make_float2(v00, v01);
                *(float2*)(C + (size_t)(row0 + 8) * N + col) = make_float2(v10, v11);
            }
        }
    }
}

// ---------------------------------------------------------------------------
// FP16 tensor-core causal flash attention.
// CTA: 128 q rows, 256 threads = 8 warps (one m16 band each), KV tiles of 64.
// QK^T: fp16x2 3-pass (scores scaled by 0.125 post-MMA); PV: P fp16 in-register
// (C-frag == A-frag layout for m16n8k16) x V hi/lo (2 passes). FFMA exp.
// Output split to fp16 hi/lo straight into g_axh/g_axl ([b,s,d]).
// ---------------------------------------------------------------------------
#define AST    72                       // 64 + 8 halves pad
#define TILE_A (64 * AST)               // halves per tile
#define STG_H  (4 * TILE_A)             // Kh, Kl, Vh, Vl
#define ATTN_SMEM (2 * STG_H * 2)       // bytes = 73728

__global__ __launch_bounds__(256, 1) void attn_f16()
{
    extern __shared__ __half smh[];
    const int tid  = threadIdx.x;
    const int lane = tid & 31;
    const int w    = tid >> 5;
    const int g    = lane >> 2;
    const int tg   = lane & 3;
    const int qt   = 15 - blockIdx.x;      // heavy CTAs first
    const int bh   = blockIdx.y;
    const int qbase = qt * 128;

    const __half* Qh = g_qh + (size_t)bh * NS * NHD;
    const __half* Ql = g_ql + (size_t)bh * NS * NHD;
    const __half* Kh = g_kh + (size_t)bh * NS * NHD;
    const __half* Kl = g_kl + (size_t)bh * NS * NHD;
    const __half* Vh = g_vh + (size_t)bh * NHD * NS;
    const __half* Vl = g_vl + (size_t)bh * NHD * NS;

    const int r0 = qbase + w * 16 + g;     // global q row of accum row 0

    // Q fragments resident in registers (4 ksteps of k16)
    uint32_t qfh[4][4], qfl[4][4];
#pragma unroll
    for (int ks = 0; ks < 4; ks++) {
        const int kb = ks * 16;
        qfh[ks][0] = ldh2(Qh + (size_t)r0 * NHD + kb + 2 * tg);
        qfh[ks][1] = ldh2(Qh + (size_t)(r0 + 8) * NHD + kb + 2 * tg);
        qfh[ks][2] = ldh2(Qh + (size_t)r0 * NHD + kb + 8 + 2 * tg);
        qfh[ks][3] = ldh2(Qh + (size_t)(r0 + 8) * NHD + kb + 8 + 2 * tg);
        qfl[ks][0] = ldh2(Ql + (size_t)r0 * NHD + kb + 2 * tg);
        qfl[ks][1] = ldh2(Ql + (size_t)(r0 + 8) * NHD + kb + 2 * tg);
        qfl[ks][2] = ldh2(Ql + (size_t)r0 * NHD + kb + 8 + 2 * tg);
        qfl[ks][3] = ldh2(Ql + (size_t)(r0 + 8) * NHD + kb + 8 + 2 * tg);
    }

    float o[8][4];
#pragma unroll
    for (int j = 0; j < 8; j++)
#pragma unroll
        for (int c = 0; c < 4; c++) o[j][c] = 0.f;
    float m[2] = {-1e30f, -1e30f};
    float l[2] = {0.f, 0.f};

    const int nt = 2 * qt + 2;

    auto load_tile = [&](int kt, int s) {
        __half* st = smh + s * STG_H;
#pragma unroll
        for (int i = 0; i < 2; i++) {
            const int idx = tid + i * 256;       // 0..511
            const int row = idx >> 3;            // 0..63
            const int q   = idx & 7;             // 8-half chunk
            const uint32_t d = smem_u32(st + row * AST + q * 8);
            cp_async16(d,                  Kh + (size_t)(kt * 64 + row) * NHD + q * 8);
            cp_async16(d + TILE_A * 2,     Kl + (size_t)(kt * 64 + row) * NHD + q * 8);
            cp_async16(d + 2 * TILE_A * 2, Vh + (size_t)row * NS + kt * 64 + q * 8);
            cp_async16(d + 3 * TILE_A * 2, Vl + (size_t)row * NS + kt * 64 + q * 8);
        }
        CP_COMMIT();
    };

    load_tile(0, 0);

    for (int kt = 0; kt < nt; kt++) {
        const int s = kt & 1;
        __syncthreads();                        // all warps done with stage s^1
        if (kt + 1 < nt) {
            load_tile(kt + 1, s ^ 1);
            asm volatile("cp.async.wait_group 1;" ::: "memory");
        } else {
            asm volatile("cp.async.wait_group 0;" ::: "memory");
        }
        __syncthreads();                        // stage s visible to all

        const __half* sKh = smh + s * STG_H;
        const __half* sKl = sKh + TILE_A;
        const __half* sVh = sKh + 2 * TILE_A;
        const __half* sVl = sKh + 3 * TILE_A;

        // ---- S = Q K^T (fp16x2, 3 passes) ----
        float sc[8][4];
#pragma unroll
        for (int j = 0; j < 8; j++)
#pragma unroll
            for (int c = 0; c < 4; c++) sc[j][c] = 0.f;

#pragma unroll
        for (int ks = 0; ks < 4; ks++) {
            const int kb = ks * 16;
            uint32_t bfh[8][2], bfl[8][2];
#pragma unroll
            for (int j = 0; j < 8; j++) {
                const int n0 = j * 8 + g;
                bfh[j][0] = ldh2(sKh + n0 * AST + kb + 2 * tg);
                bfh[j][1] = ldh2(sKh + n0 * AST + kb + 8 + 2 * tg);
                bfl[j][0] = ldh2(sKl + n0 * AST + kb + 2 * tg);
                bfl[j][1] = ldh2(sKl + n0 * AST + kb + 8 + 2 * tg);
            }
#pragma unroll
            for (int j = 0; j < 8; j++) mma_f16(sc[j], qfh[ks], bfh[j]);
#pragma unroll
            for (int j = 0; j < 8; j++) mma_f16(sc[j], qfh[ks], bfl[j]);
#pragma unroll
            for (int j = 0; j < 8; j++) mma_f16(sc[j], qfl[ks], bfh[j]);
        }

        // ---- scale + causal mask ----
#pragma unroll
        for (int j = 0; j < 8; j++)
#pragma unroll
            for (int c = 0; c < 4; c++) sc[j][c] *= SCALE;
        if (kt >= 2 * qt) {
            const int colb = kt * 64;
#pragma unroll
            for (int j = 0; j < 8; j++) {
                const int c0 = colb + j * 8 + 2 * tg;
#pragma unroll
                for (int c = 0; c < 4; c++) {
                    const int col = c0 + (c & 1);
                    const int row = (c < 2) ? r0 : r0 + 8;
                    if (col > row) sc[j][c] = -1e30f;
                }
            }
        }

        // ---- online softmax (FFMA exp) ----
#pragma unroll
        for (int r = 0; r < 2; r++) {
            float rm = -1e30f;
#pragma unroll
            for (int j = 0; j < 8; j++)
                rm = fmaxf(rm, fmaxf(sc[j][2 * r], sc[j][2 * r + 1]));
            rm = fmaxf(rm, __shfl_xor_sync(0xffffffffu, rm, 1));
            rm = fmaxf(rm, __shfl_xor_sync(0xffffffffu, rm, 2));
            const float mn   = fmaxf(m[r], rm);
            const float corr = fexp(m[r] - mn);
            m[r] = mn;
            float ps = 0.f;
#pragma unroll
            for (int j = 0; j < 8; j++) {
                const float p0 = fexp(sc[j][2 * r]     - mn);
                const float p1 = fexp(sc[j][2 * r + 1] - mn);
                sc[j][2 * r]     = p0;
                sc[j][2 * r + 1] = p1;
                ps += p0 + p1;
            }
            l[r] = l[r] * corr + ps;
#pragma unroll
            for (int j = 0; j < 8; j++) {
                o[j][2 * r]     *= corr;
                o[j][2 * r + 1] *= corr;
            }
        }

        // ---- O += P V : P converts C-frag -> A-frag purely in registers ----
#pragma unroll
        for (int ks = 0; ks < 4; ks++) {
            const int kb = ks * 16;
            uint32_t pa[4];
            pa[0] = pack_h2(sc[2 * ks][0],     sc[2 * ks][1]);
            pa[1] = pack_h2(sc[2 * ks][2],     sc[2 * ks][3]);
            pa[2] = pack_h2(sc[2 * ks + 1][0], sc[2 * ks + 1][1]);
            pa[3] = pack_h2(sc[2 * ks + 1][2], sc[2 * ks + 1][3]);
            uint32_t vfh[8][2], vfl[8][2];
#pragma unroll
            for (int j = 0; j < 8; j++) {
                const int n0 = j * 8 + g;
                vfh[j][0] = ldh2(sVh + n0 * AST + kb + 2 * tg);
                vfh[j][1] = ldh2(sVh + n0 * AST + kb + 8 + 2 * tg);
                vfl[j][0] = ldh2(sVl + n0 * AST + kb + 2 * tg);
                vfl[j][1] = ldh2(sVl + n0 * AST + kb + 8 + 2 * tg);
            }
#pragma unroll
            for (int j = 0; j < 8; j++) mma_f16(o[j], pa, vfh[j]);
#pragma unroll
            for (int j = 0; j < 8; j++) mma_f16(o[j], pa, vfl[j]);
        }
    }

    // ---- finalize: normalize, split to fp16 hi/lo, write [b,s,d] ----
#pragma unroll
    for (int r = 0; r < 2; r++) {
        float lv = l[r];
        lv += __shfl_xor_sync(0xffffffffu, lv, 1);
        lv += __shfl_xor_sync(0xffffffffu, lv, 2);
        l[r] = 1.0f / lv;
    }
    const int b = bh >> 4;
    const int h = bh & (NH - 1);
#pragma unroll
    for (int j = 0; j < 8; j++) {
        const int col = h * NHD + j * 8 + 2 * tg;
#pragma unroll
        for (int r = 0; r < 2; r++) {
            const int row = (r == 0) ? r0 : r0 + 8;
            const size_t off = ((size_t)(b * NS) + row) * ND + col;
            const float v0 = o[j][2 * r]     * l[r];
            const float v1 = o[j][2 * r + 1] * l[r];
            __half h0, l0, h1, l1;
            split_h(v0, h0, l0);
            split_h(v1, h1, l1);
            *(uint32_t*)(g_axh + off) = (uint32_t)__half_as_ushort(h0) | ((uint32_t)__half_as_ushort(h1) << 16);
            *(uint32_t*)(g_axl + off) = (uint32_t)__half_as_ushort(l0) | ((uint32_t)__half_as_ushort(l1) << 16);
        }
    }
}

// ---------------------------------------------------------------------------
// kernel_launch
// ---------------------------------------------------------------------------
extern "C" void kernel_launch(void* const* d_in, const int* in_sizes, int n_in,
                              void* d_out, int out_size)
{
    (void)in_sizes; (void)n_in; (void)out_size;
    const float* x     = (const float*)d_in[0];
    const float* Wqkv  = (const float*)d_in[1];
    const float* bqkv  = (const float*)d_in[2];
    const float* Wproj = (const float*)d_in[3];
    const float* bproj = (const float*)d_in[4];
    float* out = (float*)d_out;

    void *p_axh, *p_axl, *p_wqh, *p_wql, *p_wph, *p_wpl;
    cudaGetSymbolAddress(&p_axh, g_axh);
    cudaGetSymbolAddress(&p_axl, g_axl);
    cudaGetSymbolAddress(&p_wqh, g_wqh);
    cudaGetSymbolAddress(&p_wql, g_wql);
    cudaGetSymbolAddress(&p_wph, g_wph);
    cudaGetSymbolAddress(&p_wpl, g_wpl);
    __half* axh = (__half*)p_axh; __half* axl = (__half*)p_axl;
    __half* wqh = (__half*)p_wqh; __half* wql = (__half*)p_wql;
    __half* wph = (__half*)p_wph; __half* wpl = (__half*)p_wpl;

    static bool attr_done = false;
    if (!attr_done) {
        cudaFuncSetAttribute((const void*)gemm_f16<0>,
                             cudaFuncAttributeMaxDynamicSharedMemorySize, GEMM_SMEM);
        cudaFuncSetAttribute((const void*)gemm_f16<1>,
                             cudaFuncAttributeMaxDynamicSharedMemorySize, GEMM_SMEM);
        cudaFuncSetAttribute((const void*)attn_f16,
                             cudaFuncAttributeMaxDynamicSharedMemorySize, ATTN_SMEM);
        attr_done = true;
    }

    // 0) weight transpose+split (x32)
    {
        dim3 b(32, 8);
        tsplit16_kernel<<<dim3(3 * ND / 32, ND / 32), b>>>(Wqkv, wqh, wql, ND, 3 * ND);
        tsplit16_kernel<<<dim3(ND / 32, ND / 32), b>>>(Wproj, wph, wpl, ND, ND);
    }

    // 1) split x into fp16 hi/lo
    split16_kernel<<<2048, 256>>>(x, axh, axl, NB * NS * ND);

    // 2) QKV GEMM -> split-scatter q/k/v (v transposed)
    gemm_f16<0><<<dim3(3 * ND / 128, NB * NS / 128), 256, GEMM_SMEM>>>(
        axh, axl, wqh, wql, bqkv, nullptr, NB * NS, 3 * ND, ND);

    // 3) fp16 tensor-core causal flash attention -> g_axh/g_axl (pre-split)
    attn_f16<<<dim3(NS / 128, NB * NH), 256, ATTN_SMEM>>>();

    // 4) output projection -> d_out
    gemm_f16<1><<<dim3(ND / 128, NB * NS / 128), 256, GEMM_SMEM>>>(
        axh, axl, wph, wpl, bproj, out, NB * NS, ND, ND);
}

// round 7
// speedup vs baseline: 2.9244x; 1.0230x over previous
#include <cuda_runtime.h>
#include <cuda_fp16.h>
#include <math.h>
#include <stdint.h>

// Problem constants
#define NB  2
#define NS  2048
#define ND  1024
#define NH  16
#define NHD 64
#define SCALE  0.125f    // 1/sqrt(64), applied to scores post-MMA
#define WSCALE 32.0f     // weight pre-scale (keeps w_lo out of fp16 subnormals)
#define INVW   0.03125f

// ---------------------------------------------------------------------------
// Scratch (allocation-free contract: __device__ globals)
// ---------------------------------------------------------------------------
__device__ __half g_qh[NB * NH * NS * NHD];   // [bh][s][hd]  (unscaled hi)
__device__ __half g_ql[NB * NH * NS * NHD];
__device__ __half g_kh[NB * NH * NS * NHD];   // [bh][s][hd]
__device__ __half g_kl[NB * NH * NS * NHD];
__device__ __half g_vh[NB * NH * NS * NHD];   // [bh][hd][s]  (transposed)
__device__ __half g_vl[NB * NH * NS * NHD];
__device__ __half g_axh[NB * NS * ND];        // activation hi/lo (x, then attn out)
__device__ __half g_axl[NB * NS * ND];
__device__ __half g_wqh[3 * ND * ND];         // W_qkv^T * 32, hi   [3072 x 1024]
__device__ __half g_wql[3 * ND * ND];
__device__ __half g_wph[ND * ND];             // W_proj^T * 32, hi  [1024 x 1024]
__device__ __half g_wpl[ND * ND];

// ---------------------------------------------------------------------------
// Helpers
// ---------------------------------------------------------------------------
__device__ __forceinline__ uint32_t smem_u32(const void* p) {
    uint32_t a;
    asm("{ .reg .u64 t; cvta.to.shared.u64 t, %1; cvt.u32.u64 %0, t; }"
        : "=r"(a) : "l"(p));
    return a;
}

__device__ __forceinline__ void cp_async16(uint32_t saddr, const void* gptr) {
    asm volatile("cp.async.cg.shared.global [%0], [%1], 16;" :: "r"(saddr), "l"(gptr));
}
#define CP_COMMIT() asm volatile("cp.async.commit_group;" ::: "memory")

__device__ __forceinline__ uint32_t ldh2(const __half* p) {
    return *reinterpret_cast<const uint32_t*>(p);
}

__device__ __forceinline__ uint32_t pack_h2(float a, float b) {
    __half2 h = __floats2half2_rn(a, b);
    return *reinterpret_cast<uint32_t*>(&h);
}

__device__ __forceinline__ void split_h(float v, __half& hi, __half& lo) {
    hi = __float2half_rn(v);
    lo = __float2half_rn(v - __half2float(hi));
}

// ldmatrix: 4x (8x8 b16) tiles; per-lane row addresses
__device__ __forceinline__ void ldsm_x4(uint32_t& r0, uint32_t& r1,
                                        uint32_t& r2, uint32_t& r3, uint32_t addr) {
    asm volatile("ldmatrix.sync.aligned.m8n8.x4.shared.b16 {%0,%1,%2,%3}, [%4];"
        : "=r"(r0), "=r"(r1), "=r"(r2), "=r"(r3) : "r"(addr));
}

// m16n8k16 f16 MMA, fp32 accumulate in-place
__device__ __forceinline__ void mma_f16(float* d, const uint32_t* a, const uint32_t* b) {
    asm volatile(
        "mma.sync.aligned.m16n8k16.row.col.f32.f16.f16.f32 "
        "{%0,%1,%2,%3}, {%4,%5,%6,%7}, {%8,%9}, {%0,%1,%2,%3};"
        : "+f"(d[0]), "+f"(d[1]), "+f"(d[2]), "+f"(d[3])
        : "r"(a[0]), "r"(a[1]), "r"(a[2]), "r"(a[3]), "r"(b[0]), "r"(b[1]));
}

// FFMA-only exp (finite x; clamp handles big negatives). rel err ~2.4e-6.
__device__ __forceinline__ float fexp(float x) {
    x = fmaxf(x, -60.0f);
    const float y = x * 1.44269504f;
    const float t = y + 12582912.0f;              // 1.5 * 2^23
    const int   n = __float_as_int(t) - 0x4B400000;
    const float f = y - (t - 12582912.0f);
    float p = 1.33335581e-3f;
    p = fmaf(p, f, 9.61812910e-3f);
    p = fmaf(p, f, 5.55041087e-2f);
    p = fmaf(p, f, 2.40226510e-1f);
    p = fmaf(p, f, 6.93147182e-1f);
    p = fmaf(p, f, 1.0f);
    return __int_as_float(__float_as_int(p) + (n << 23));
}

// ---------------------------------------------------------------------------
// Prep kernels
// ---------------------------------------------------------------------------
__global__ void split16_kernel(const float* __restrict__ in,
                               __half* __restrict__ hi, __half* __restrict__ lo, int n) {
    for (int i = blockIdx.x * blockDim.x + threadIdx.x; i < n; i += gridDim.x * blockDim.x) {
        __half h, l;
        split_h(in[i], h, l);
        hi[i] = h;
        lo[i] = l;
    }
}

// W [K,N] row-major -> T [N,K] row-major, scaled by WSCALE, fp16 hi/lo split
__global__ __launch_bounds__(256) void tsplit16_kernel(
    const float* __restrict__ W, __half* __restrict__ Thi, __half* __restrict__ Tlo,
    int K, int N) {
    __shared__ float tile[32][33];
    const int tx = threadIdx.x;
    const int ty = threadIdx.y;
    const int n0 = blockIdx.x * 32;
    const int k0 = blockIdx.y * 32;
#pragma unroll
    for (int i = 0; i < 32; i += 8)
        tile[ty + i][tx] = W[(size_t)(k0 + ty + i) * N + n0 + tx];
    __syncthreads();
#pragma unroll
    for (int i = 0; i < 32; i += 8) {
        float v = tile[tx][ty + i] * WSCALE;
        __half h, l;
        split_h(v, h, l);
        Thi[(size_t)(n0 + ty + i) * K + k0 + tx] = h;
        Tlo[(size_t)(n0 + ty + i) * K + k0 + tx] = l;
    }
}

// ---------------------------------------------------------------------------
// FP16x2 (3-pass) mma.sync GEMM with ldmatrix fragment loads.
// C[M,N] = (A[M,K] * B[N,K]^T) / 32.  128x128 tile/CTA, 256 threads,
// warps 2(m) x 4(n), warp tile 64x32, K-chunk 64, double-buffered cp.async.
// MODE 0: split-scatter QKV;  MODE 1: C = acc/32 + bias (fp32)
// ---------------------------------------------------------------------------
#define KC     64
#define ROWH   72                       // 64 + 8 halves pad
#define TILEH  (128 * ROWH)             // halves per tile
#define STAGEH (4 * TILEH)              // Ah, Al, Bh, Bl
#define GEMM_SMEM (2 * STAGEH * 2)      // bytes = 147456

template <int MODE>
__global__ __launch_bounds__(256, 1) void gemm_f16(
    const __half* __restrict__ Ahi, const __half* __restrict__ Alo,
    const __half* __restrict__ Bhi, const __half* __restrict__ Blo,
    const float* __restrict__ bias, float* __restrict__ C,
    int M, int N, int K)
{
    extern __shared__ __half smh[];
    const int tid  = threadIdx.x;
    const int lane = tid & 31;
    const int wid  = tid >> 5;
    const int wm   = wid >> 2;
    const int wn   = wid & 3;
    const int g    = lane >> 2;
    const int tg   = lane & 3;
    const int bm = blockIdx.y * 128;
    const int bn = blockIdx.x * 128;

    // ldmatrix per-lane byte offsets (within a 16x16 tile at given base)
    const int la = lane & 7;
    const uint32_t aoff = (uint32_t)(((la + ((lane >> 3) & 1) * 8) * ROWH
                                     + ((lane >> 4) & 1) * 8) * 2);
    const uint32_t boff = (uint32_t)(((la + ((lane >> 4) & 1) * 8) * ROWH
                                     + ((lane >> 3) & 1) * 8) * 2);

    const __half* srcT[4] = {Ahi, Alo, Bhi, Blo};

    auto load_stage = [&](int c, int s) {
        const int k0 = c * KC;
        __half* stage = smh + s * STAGEH;
#pragma unroll
        for (int t = 0; t < 4; t++) {
            const __half* src = srcT[t];
            const int rbase = (t < 2) ? bm : bn;
            __half* dst = stage + t * TILEH;
#pragma unroll
            for (int i = 0; i < 4; i++) {
                const int idx = tid + i * 256;     // 0..1023
                const int r = idx >> 3;
                const int q = idx & 7;             // 8 halves (16B) per chunk
                cp_async16(smem_u32(dst + r * ROWH + q * 8),
                           src + (size_t)(rbase + r) * K + k0 + q * 8);
            }
        }
        CP_COMMIT();
    };

    float acc[4][4][4];
#pragma unroll
    for (int i = 0; i < 4; i++)
#pragma unroll
        for (int j = 0; j < 4; j++)
#pragma unroll
            for (int kq = 0; kq < 4; kq++) acc[i][j][kq] = 0.f;

    const int NCH = K / KC;
    load_stage(0, 0);

    for (int c = 0; c < NCH; c++) {
        const int s = c & 1;
        if (c + 1 < NCH) {
            load_stage(c + 1, (c + 1) & 1);
            asm volatile("cp.async.wait_group 1;" ::: "memory");
        } else {
            asm volatile("cp.async.wait_group 0;" ::: "memory");
        }
        __syncthreads();

        const uint32_t sA = smem_u32(smh + s * STAGEH);          // Ah
        const uint32_t sB = sA + 2 * TILEH * 2;                  // Bh (bytes)

#pragma unroll
        for (int ks = 0; ks < 4; ks++) {
            const int kb = ks * 16;
            uint32_t ah[4][4], al[4][4], bh[4][2], bl[4][2];
#pragma unroll
            for (int am = 0; am < 4; am++) {
                const uint32_t base = sA + (uint32_t)(((wm * 64 + am * 16) * ROWH + kb) * 2);
                ldsm_x4(ah[am][0], ah[am][1], ah[am][2], ah[am][3], base + aoff);
                ldsm_x4(al[am][0], al[am][1], al[am][2], al[am][3],
                        base + (uint32_t)(TILEH * 2) + aoff);
            }
#pragma unroll
            for (int p = 0; p < 2; p++) {
                const uint32_t base = sB + (uint32_t)(((wn * 32 + p * 16) * ROWH + kb) * 2);
                ldsm_x4(bh[2 * p][0], bh[2 * p][1], bh[2 * p + 1][0], bh[2 * p + 1][1],
                        base + boff);
                ldsm_x4(bl[2 * p][0], bl[2 * p][1], bl[2 * p + 1][0], bl[2 * p + 1][1],
                        base + (uint32_t)(TILEH * 2) + boff);
            }
#pragma unroll
            for (int am = 0; am < 4; am++)
#pragma unroll
                for (int an = 0; an < 4; an++)
                    mma_f16(acc[am][an], ah[am], bh[an]);
#pragma unroll
            for (int am = 0; am < 4; am++)
#pragma unroll
                for (int an = 0; an < 4; an++)
                    mma_f16(acc[am][an], ah[am], bl[an]);
#pragma unroll
            for (int am = 0; am < 4; am++)
#pragma unroll
                for (int an = 0; an < 4; an++)
                    mma_f16(acc[am][an], al[am], bh[an]);
        }
        __syncthreads();
    }

    // ---- epilogue ----
#pragma unroll
    for (int am = 0; am < 4; am++) {
        const int row0 = bm + wm * 64 + am * 16 + g;
#pragma unroll
        for (int an = 0; an < 4; an++) {
            const int col = bn + wn * 32 + an * 8 + 2 * tg;
            const float v00 = acc[am][an][0] * INVW + bias[col];
            const float v01 = acc[am][an][1] * INVW + bias[col + 1];
            const float v10 = acc[am][an][2] * INVW + bias[col];
            const float v11 = acc[am][an][3] * INVW + bias[col + 1];
            if (MODE == 0) {
#pragma unroll
                for (int e = 0; e < 4; e++) {
                    const int m = (e < 2) ? row0 : row0 + 8;
                    const int n = col + (e & 1);
                    const float v = (e == 0) ? v00 : (e == 1) ? v01 : (e == 2) ? v10 : v11;
                    const int b = m >> 11;            // NS = 2048
                    const int srow = m & (NS - 1);
                    const int which = n >> 10;        // ND = 1024
                    const int dcol  = n & (ND - 1);
                    const int h  = dcol >> 6;         // NHD = 64
                    const int hd = dcol & 63;
                    const int bhh = b * NH + h;
                    __half hi, lo;
                    split_h(v, hi, lo);
                    if (which == 0) {
                        const size_t o = ((size_t)bhh * NS + srow) * NHD + hd;
                        g_qh[o] = hi; g_ql[o] = lo;
                    } else if (which == 1) {
                        const size_t o = ((size_t)bhh * NS + srow) * NHD + hd;
                        g_kh[o] = hi; g_kl[o] = lo;
                    } else {
                        const size_t o = ((size_t)bhh * NHD + hd) * NS + srow;
                        g_vh[o] = hi; g_vl[o] = lo;
                    }
                }
            } else {
                *(float2*)(C + (size_t)row0 * N + col)       = make_float2(v00, v01);
                *(float2*)(C + (size_t)(row0 + 8) * N + col) = make_float2(v10, v11);
            }
        }
    }
}

// ---------------------------------------------------------------------------
// FP16 tensor-core causal flash attention (ldmatrix fragment loads).
// CTA: 128 q rows, 256 threads = 8 warps (one m16 band each), KV tiles of 64.
// ---------------------------------------------------------------------------
#define AST    72                       // 64 + 8 halves pad
#define TILE_A (64 * AST)               // halves per tile
#define STG_H  (4 * TILE_A)             // Kh, Kl, Vh, Vl
#define ATTN_SMEM (2 * STG_H * 2)       // bytes = 73728

__global__ __launch_bounds__(256, 1) void attn_f16()
{
    extern __shared__ __half smh[];
    const int tid  = threadIdx.x;
    const int lane = tid & 31;
    const int w    = tid >> 5;
    const int g    = lane >> 2;
    const int tg   = lane & 3;
    const int qt   = 15 - blockIdx.x;      // heavy CTAs first
    const int bh   = blockIdx.y;
    const int qbase = qt * 128;

    const int la = lane & 7;
    const uint32_t boff = (uint32_t)(((la + ((lane >> 4) & 1) * 8) * AST
                                     + ((lane >> 3) & 1) * 8) * 2);

    const __half* Qh = g_qh + (size_t)bh * NS * NHD;
    const __half* Ql = g_ql + (size_t)bh * NS * NHD;
    const __half* Kh = g_kh + (size_t)bh * NS * NHD;
    const __half* Kl = g_kl + (size_t)bh * NS * NHD;
    const __half* Vh = g_vh + (size_t)bh * NHD * NS;
    const __half* Vl = g_vl + (size_t)bh * NHD * NS;

    const int r0 = qbase + w * 16 + g;     // global q row of accum row 0

    // Q fragments resident in registers (4 ksteps of k16)
    uint32_t qfh[4][4], qfl[4][4];
#pragma unroll
    for (int ks = 0; ks < 4; ks++) {
        const int kb = ks * 16;
        qfh[ks][0] = ldh2(Qh + (size_t)r0 * NHD + kb + 2 * tg);
        qfh[ks][1] = ldh2(Qh + (size_t)(r0 + 8) * NHD + kb + 2 * tg);
        qfh[ks][2] = ldh2(Qh + (size_t)r0 * NHD + kb + 8 + 2 * tg);
        qfh[ks][3] = ldh2(Qh + (size_t)(r0 + 8) * NHD + kb + 8 + 2 * tg);
        qfl[ks][0] = ldh2(Ql + (size_t)r0 * NHD + kb + 2 * tg);
        qfl[ks][1] = ldh2(Ql + (size_t)(r0 + 8) * NHD + kb + 2 * tg);
        qfl[ks][2] = ldh2(Ql + (size_t)r0 * NHD + kb + 8 + 2 * tg);
        qfl[ks][3] = ldh2(Ql + (size_t)(r0 + 8) * NHD + kb + 8 + 2 * tg);
    }

    float o[8][4];
#pragma unroll
    for (int j = 0; j < 8; j++)
#pragma unroll
        for (int c = 0; c < 4; c++) o[j][c] = 0.f;
    float m[2] = {-1e30f, -1e30f};
    float l[2] = {0.f, 0.f};

    const int nt = 2 * qt + 2;

    auto load_tile = [&](int kt, int s) {
        __half* st = smh + s * STG_H;
#pragma unroll
        for (int i = 0; i < 2; i++) {
            const int idx = tid + i * 256;       // 0..511
            const int row = idx >> 3;            // 0..63
            const int q   = idx & 7;             // 8-half chunk
            const uint32_t d = smem_u32(st + row * AST + q * 8);
            cp_async16(d,                  Kh + (size_t)(kt * 64 + row) * NHD + q * 8);
            cp_async16(d + TILE_A * 2,     Kl + (size_t)(kt * 64 + row) * NHD + q * 8);
            cp_async16(d + 2 * TILE_A * 2, Vh + (size_t)row * NS + kt * 64 + q * 8);
            cp_async16(d + 3 * TILE_A * 2, Vl + (size_t)row * NS + kt * 64 + q * 8);
        }
        CP_COMMIT();
    };

    load_tile(0, 0);

    for (int kt = 0; kt < nt; kt++) {
        const int s = kt & 1;
        __syncthreads();                        // all warps done with stage s^1
        if (kt + 1 < nt) {
            load_tile(kt + 1, s ^ 1);
            asm volatile("cp.async.wait_group 1;" ::: "memory");
        } else {
            asm volatile("cp.async.wait_group 0;" ::: "memory");
        }
        __syncthreads();                        // stage s visible to all

        const uint32_t sK = smem_u32(smh + s * STG_H);           // Kh (bytes)
        const uint32_t sV = sK + 2 * TILE_A * 2;                 // Vh

        // ---- S = Q K^T (fp16x2, 3 passes) ----
        float sc[8][4];
#pragma unroll
        for (int j = 0; j < 8; j++)
#pragma unroll
            for (int c = 0; c < 4; c++) sc[j][c] = 0.f;

#pragma unroll
        for (int ks = 0; ks < 4; ks++) {
            const int kb = ks * 16;
            uint32_t bfh[8][2], bfl[8][2];
#pragma unroll
            for (int p = 0; p < 4; p++) {
                const uint32_t base = sK + (uint32_t)((p * 16 * AST + kb) * 2);
                ldsm_x4(bfh[2 * p][0], bfh[2 * p][1], bfh[2 * p + 1][0], bfh[2 * p + 1][1],
                        base + boff);
                ldsm_x4(bfl[2 * p][0], bfl[2 * p][1], bfl[2 * p + 1][0], bfl[2 * p + 1][1],
                        base + (uint32_t)(TILE_A * 2) + boff);
            }
#pragma unroll
            for (int j = 0; j < 8; j++) mma_f16(sc[j], qfh[ks], bfh[j]);
#pragma unroll
            for (int j = 0; j < 8; j++) mma_f16(sc[j], qfh[ks], bfl[j]);
#pragma unroll
            for (int j = 0; j < 8; j++) mma_f16(sc[j], qfl[ks], bfh[j]);
        }

        // ---- scale + causal mask ----
#pragma unroll
        for (int j = 0; j < 8; j++)
#pragma unroll
            for (int c = 0; c < 4; c++) sc[j][c] *= SCALE;
        if (kt >= 2 * qt) {
            const int colb = kt * 64;
#pragma unroll
            for (int j = 0; j < 8; j++) {
                const int c0 = colb + j * 8 + 2 * tg;
#pragma unroll
                for (int c = 0; c < 4; c++) {
                    const int col = c0 + (c & 1);
                    const int row = (c < 2) ? r0 : r0 + 8;
                    if (col > row) sc[j][c] = -1e30f;
                }
            }
        }

        // ---- online softmax (FFMA exp) ----
#pragma unroll
        for (int r = 0; r < 2; r++) {
            float rm = -1e30f;
#pragma unroll
            for (int j = 0; j < 8; j++)
                rm = fmaxf(rm, fmaxf(sc[j][2 * r], sc[j][2 * r + 1]));
            rm = fmaxf(rm, __shfl_xor_sync(0xffffffffu, rm, 1));
            rm = fmaxf(rm, __shfl_xor_sync(0xffffffffu, rm, 2));
            const float mn   = fmaxf(m[r], rm);
            const float corr = fexp(m[r] - mn);
            m[r] = mn;
            float ps = 0.f;
#pragma unroll
            for (int j = 0; j < 8; j++) {
                const float p0 = fexp(sc[j][2 * r]     - mn);
                const float p1 = fexp(sc[j][2 * r + 1] - mn);
                sc[j][2 * r]     = p0;
                sc[j][2 * r + 1] = p1;
                ps += p0 + p1;
            }
            l[r] = l[r] * corr + ps;
#pragma unroll
            for (int j = 0; j < 8; j++) {
                o[j][2 * r]     *= corr;
                o[j][2 * r + 1] *= corr;
            }
        }

        // ---- O += P V : P converts C-frag -> A-frag purely in registers ----
#pragma unroll
        for (int ks = 0; ks < 4; ks++) {
            const int kb = ks * 16;
            uint32_t pa[4];
            pa[0] = pack_h2(sc[2 * ks][0],     sc[2 * ks][1]);
            pa[1] = pack_h2(sc[2 * ks][2],     sc[2 * ks][3]);
            pa[2] = pack_h2(sc[2 * ks + 1][0], sc[2 * ks + 1][1]);
            pa[3] = pack_h2(sc[2 * ks + 1][2], sc[2 * ks + 1][3]);
            uint32_t vfh[8][2], vfl[8][2];
#pragma unroll
            for (int p = 0; p < 4; p++) {
                const uint32_t base = sV + (uint32_t)((p * 16 * AST + kb) * 2);
                ldsm_x4(vfh[2 * p][0], vfh[2 * p][1], vfh[2 * p + 1][0], vfh[2 * p + 1][1],
                        base + boff);
                ldsm_x4(vfl[2 * p][0], vfl[2 * p][1], vfl[2 * p + 1][0], vfl[2 * p + 1][1],
                        base + (uint32_t)(TILE_A * 2) + boff);
            }
#pragma unroll
            for (int j = 0; j < 8; j++) mma_f16(o[j], pa, vfh[j]);
#pragma unroll
            for (int j = 0; j < 8; j++) mma_f16(o[j], pa, vfl[j]);
        }
    }

    // ---- finalize: normalize, split to fp16 hi/lo, write [b,s,d] ----
#pragma unroll
    for (int r = 0; r < 2; r++) {
        float lv = l[r];
        lv += __shfl_xor_sync(0xffffffffu, lv, 1);
        lv += __shfl_xor_sync(0xffffffffu, lv, 2);
        l[r] = 1.0f / lv;
    }
    const int b = bh >> 4;
    const int h = bh & (NH - 1);
#pragma unroll
    for (int j = 0; j < 8; j++) {
        const int col = h * NHD + j * 8 + 2 * tg;
#pragma unroll
        for (int r = 0; r < 2; r++) {
            const int row = (r == 0) ? r0 : r0 + 8;
            const size_t off = ((size_t)(b * NS) + row) * ND + col;
            const float v0 = o[j][2 * r]     * l[r];
            const float v1 = o[j][2 * r + 1] * l[r];
            __half h0, l0, h1, l1;
            split_h(v0, h0, l0);
            split_h(v1, h1, l1);
            *(uint32_t*)(g_axh + off) = (uint32_t)__half_as_ushort(h0) | ((uint32_t)__half_as_ushort(h1) << 16);
            *(uint32_t*)(g_axl + off) = (uint32_t)__half_as_ushort(l0) | ((uint32_t)__half_as_ushort(l1) << 16);
        }
    }
}

// ---------------------------------------------------------------------------
// kernel_launch
// ---------------------------------------------------------------------------
extern "C" void kernel_launch(void* const* d_in, const int* in_sizes, int n_in,
                              void* d_out, int out_size)
{
    (void)in_sizes; (void)n_in; (void)out_size;
    const float* x     = (const float*)d_in[0];
    const float* Wqkv  = (const float*)d_in[1];
    const float* bqkv  = (const float*)d_in[2];
    const float* Wproj = (const float*)d_in[3];
    const float* bproj = (const float*)d_in[4];
    float* out = (float*)d_out;

    void *p_axh, *p_axl, *p_wqh, *p_wql, *p_wph, *p_wpl;
    cudaGetSymbolAddress(&p_axh, g_axh);
    cudaGetSymbolAddress(&p_axl, g_axl);
    cudaGetSymbolAddress(&p_wqh, g_wqh);
    cudaGetSymbolAddress(&p_wql, g_wql);
    cudaGetSymbolAddress(&p_wph, g_wph);
    cudaGetSymbolAddress(&p_wpl, g_wpl);
    __half* axh = (__half*)p_axh; __half* axl = (__half*)p_axl;
    __half* wqh = (__half*)p_wqh; __half* wql = (__half*)p_wql;
    __half* wph = (__half*)p_wph; __half* wpl = (__half*)p_wpl;

    static bool attr_done = false;
    if (!attr_done) {
        cudaFuncSetAttribute((const void*)gemm_f16<0>,
                             cudaFuncAttributeMaxDynamicSharedMemorySize, GEMM_SMEM);
        cudaFuncSetAttribute((const void*)gemm_f16<1>,
                             cudaFuncAttributeMaxDynamicSharedMemorySize, GEMM_SMEM);
        cudaFuncSetAttribute((const void*)attn_f16,
                             cudaFuncAttributeMaxDynamicSharedMemorySize, ATTN_SMEM);
        attr_done = true;
    }

    // 0) weight transpose+split (x32)
    {
        dim3 b(32, 8);
        tsplit16_kernel<<<dim3(3 * ND / 32, ND / 32), b>>>(Wqkv, wqh, wql, ND, 3 * ND);
        tsplit16_kernel<<<dim3(ND / 32, ND / 32), b>>>(Wproj, wph, wpl, ND, ND);
    }

    // 1) split x into fp16 hi/lo
    split16_kernel<<<2048, 256>>>(x, axh, axl, NB * NS * ND);

    // 2) QKV GEMM -> split-scatter q/k/v (v transposed)
    gemm_f16<0><<<dim3(3 * ND / 128, NB * NS / 128), 256, GEMM_SMEM>>>(
        axh, axl, wqh, wql, bqkv, nullptr, NB * NS, 3 * ND, ND);

    // 3) fp16 tensor-core causal flash attention -> g_axh/g_axl (pre-split)
    attn_f16<<<dim3(NS / 128, NB * NH), 256, ATTN_SMEM>>>();

    // 4) output projection -> d_out
    gemm_f16<1><<<dim3(ND / 128, NB * NS / 128), 256, GEMM_SMEM>>>(
        axh, axl, wph, wpl, bproj, out, NB * NS, ND, ND);
}